// round 1
// baseline (speedup 1.0000x reference)
#include <cuda_runtime.h>
#include <cstdint>
#include <cstddef>

// Problem constants
#define NB      2
#define SQL     4096
#define SKL     4096
#define SQD     512
#define SCD     768
#define NHEADS  8
#define HDIM    64
#define DINNER  512
#define MROWS   (NB*SQL)   // 8192

// Scratch (allocation-free rule: __device__ globals)
__device__ float g_Q[(size_t)MROWS * DINNER];
__device__ float g_K[(size_t)MROWS * DINNER];
__device__ float g_V[(size_t)MROWS * DINNER];
__device__ float g_A[(size_t)MROWS * DINNER];

// ---------------------------------------------------------------------------
// helpers
// ---------------------------------------------------------------------------
__device__ __forceinline__ unsigned f2tf(float x) {
    unsigned u;
    asm("cvt.rna.tf32.f32 %0, %1;" : "=r"(u) : "f"(x));
    return u;
}
__device__ __forceinline__ float tf32r(float x) { return __uint_as_float(f2tf(x)); }

// D = A(16x8, tf32, row) * B(8x8, tf32, col) + C, fp32 accum
__device__ __forceinline__ void mma8(float* c,
                                     unsigned a0, unsigned a1, unsigned a2, unsigned a3,
                                     unsigned b0, unsigned b1) {
    asm volatile(
        "mma.sync.aligned.m16n8k8.row.col.f32.tf32.tf32.f32 "
        "{%0,%1,%2,%3}, {%4,%5,%6,%7}, {%8,%9}, {%0,%1,%2,%3};\n"
        : "+f"(c[0]), "+f"(c[1]), "+f"(c[2]), "+f"(c[3])
        : "r"(a0), "r"(a1), "r"(a2), "r"(a3), "r"(b0), "r"(b1));
}

// ---------------------------------------------------------------------------
// Generic TF32 GEMM: C[M,N] = A[M,K] @ B[K,N] (+bias), all fp32 row-major.
// BM=128, BN=128, BK=16, 256 threads (8 warps as 2x4), warp tile 64x32.
// Requires M%128==0, N%128==0, K%16==0 (true for all shapes here).
// ---------------------------------------------------------------------------
#define GBM 128
#define GBN 128
#define GBK 16
#define ASTR 20    // conflict-free for A-frag pattern (g*20+t distinct mod 32)
#define BSTR 136   // conflict-free for B-frag pattern (t*8+g distinct mod 32)

__global__ __launch_bounds__(256) void gemm_tf32(
    const float* __restrict__ A, const float* __restrict__ B,
    float* __restrict__ C, const float* __restrict__ bias,
    int M, int N, int K)
{
    __shared__ __align__(16) float As[GBM * ASTR];
    __shared__ __align__(16) float Bs[GBK * BSTR];

    const int tid  = threadIdx.x;
    const int warp = tid >> 5, lane = tid & 31;
    const int g = lane >> 2, t = lane & 3;
    const int wm = warp >> 2, wn = warp & 3;      // 2 x 4 warp grid
    const int mBase = blockIdx.y * GBM;
    const int nBase = blockIdx.x * GBN;

    float acc[4][4][4];
#pragma unroll
    for (int i = 0; i < 4; i++)
#pragma unroll
        for (int j = 0; j < 4; j++)
#pragma unroll
            for (int c = 0; c < 4; c++) acc[i][j][c] = 0.f;

    for (int k0 = 0; k0 < K; k0 += GBK) {
        // A tile: 128x16 = 512 float4, 2 per thread
#pragma unroll
        for (int i = 0; i < 2; i++) {
            int idx = tid + i * 256;
            int r = idx >> 2, c4 = (idx & 3) * 4;
            float4 v = *(const float4*)(A + (size_t)(mBase + r) * K + k0 + c4);
            v.x = tf32r(v.x); v.y = tf32r(v.y); v.z = tf32r(v.z); v.w = tf32r(v.w);
            *(float4*)(As + r * ASTR + c4) = v;
        }
        // B tile: 16x128 = 512 float4, 2 per thread
#pragma unroll
        for (int i = 0; i < 2; i++) {
            int idx = tid + i * 256;
            int r = idx >> 5, c4 = (idx & 31) * 4;
            float4 v = *(const float4*)(B + (size_t)(k0 + r) * N + nBase + c4);
            v.x = tf32r(v.x); v.y = tf32r(v.y); v.z = tf32r(v.z); v.w = tf32r(v.w);
            *(float4*)(Bs + r * BSTR + c4) = v;
        }
        __syncthreads();

#pragma unroll
        for (int kk = 0; kk < 2; kk++) {
            unsigned af[4][4];
#pragma unroll
            for (int mf = 0; mf < 4; mf++) {
                int rb = (wm * 64 + mf * 16 + g) * ASTR + kk * 8 + t;
                af[mf][0] = __float_as_uint(As[rb]);
                af[mf][1] = __float_as_uint(As[rb + 8 * ASTR]);
                af[mf][2] = __float_as_uint(As[rb + 4]);
                af[mf][3] = __float_as_uint(As[rb + 8 * ASTR + 4]);
            }
            unsigned bf[4][2];
#pragma unroll
            for (int nf = 0; nf < 4; nf++) {
                int cb = wn * 32 + nf * 8 + g;
                bf[nf][0] = __float_as_uint(Bs[(kk * 8 + t) * BSTR + cb]);
                bf[nf][1] = __float_as_uint(Bs[(kk * 8 + t + 4) * BSTR + cb]);
            }
#pragma unroll
            for (int mf = 0; mf < 4; mf++)
#pragma unroll
                for (int nf = 0; nf < 4; nf++)
                    mma8(acc[mf][nf], af[mf][0], af[mf][1], af[mf][2], af[mf][3],
                         bf[nf][0], bf[nf][1]);
        }
        __syncthreads();
    }

    // epilogue (+ optional bias)
#pragma unroll
    for (int mf = 0; mf < 4; mf++) {
        int r0 = mBase + wm * 64 + mf * 16 + g;
#pragma unroll
        for (int nf = 0; nf < 4; nf++) {
            int col = nBase + wn * 32 + nf * 8 + 2 * t;
            float b0 = 0.f, b1 = 0.f;
            if (bias) { b0 = bias[col]; b1 = bias[col + 1]; }
            *(float2*)(C + (size_t)r0 * N + col) =
                make_float2(acc[mf][nf][0] + b0, acc[mf][nf][1] + b1);
            *(float2*)(C + (size_t)(r0 + 8) * N + col) =
                make_float2(acc[mf][nf][2] + b0, acc[mf][nf][3] + b1);
        }
    }
}

// ---------------------------------------------------------------------------
// Flash attention, TF32 mma. One CTA = (b, h, 128 q-rows). 8 warps, each owns
// 16 q-rows (softmax fully intra-warp). KL processed in 64-key tiles.
// ---------------------------------------------------------------------------
#define KSTR 68   // Ks row stride: g*4+t distinct mod 32 -> conflict-free B-frags
#define VSTR 72   // Vs row stride: t*8+g distinct mod 32 -> conflict-free B-frags
#define PSTR 68   // Ps row stride: g*4+t distinct mod 32 -> conflict-free A-frags
#define ATT_SMEM ((64*KSTR + 64*VSTR + 8*16*PSTR) * 4)   // 70656 bytes

__global__ __launch_bounds__(256) void flash_attn(
    const float* __restrict__ Q, const float* __restrict__ Kg,
    const float* __restrict__ Vg, float* __restrict__ O)
{
    extern __shared__ __align__(16) float sm[];
    float* Ks = sm;                 // [64][KSTR]  K tile (tf32-rounded)
    float* Vs = sm + 64 * KSTR;     // [64][VSTR]  V tile
    float* Ps = Vs + 64 * VSTR;     // per-warp [16][PSTR] P tile

    const int tid  = threadIdx.x;
    const int warp = tid >> 5, lane = tid & 31;
    const int g = lane >> 2, t = lane & 3;
    const int qt = blockIdx.x, h = blockIdx.y, b = blockIdx.z;
    const float scale = 0.125f;     // 64^-0.5

    const float* Qb = Q  + (size_t)b * SQL * DINNER + h * HDIM;
    const float* Kb = Kg + (size_t)b * SKL * DINNER + h * HDIM;
    const float* Vb = Vg + (size_t)b * SKL * DINNER + h * HDIM;
    float*       Ob = O  + (size_t)b * SQL * DINNER + h * HDIM;
    float*       Pw = Ps + warp * 16 * PSTR;

    const int q0 = qt * 128 + warp * 16 + g;   // rows q0 (c0/c1) and q0+8 (c2/c3)

    // Q fragments resident in registers for the whole KL loop (scale folded in)
    unsigned qf[8][4];
#pragma unroll
    for (int kk = 0; kk < 8; kk++) {
        int c = kk * 8 + t;
        qf[kk][0] = f2tf(Qb[(size_t)q0 * DINNER + c] * scale);
        qf[kk][1] = f2tf(Qb[(size_t)(q0 + 8) * DINNER + c] * scale);
        qf[kk][2] = f2tf(Qb[(size_t)q0 * DINNER + c + 4] * scale);
        qf[kk][3] = f2tf(Qb[(size_t)(q0 + 8) * DINNER + c + 4] * scale);
    }

    float oacc[8][4];
#pragma unroll
    for (int nf = 0; nf < 8; nf++)
#pragma unroll
        for (int c = 0; c < 4; c++) oacc[nf][c] = 0.f;

    float m0 = -1e30f, m1 = -1e30f, l0 = 0.f, l1 = 0.f;

    for (int kb = 0; kb < SKL; kb += 64) {
        __syncthreads();   // previous iteration fully done with Ks/Vs
        // load K,V 64x64 tiles (tf32-rounded at store)
#pragma unroll
        for (int i = 0; i < 4; i++) {
            int idx = tid + i * 256;
            int r = idx >> 4, c4 = (idx & 15) * 4;
            float4 kv = *(const float4*)(Kb + (size_t)(kb + r) * DINNER + c4);
            kv.x = tf32r(kv.x); kv.y = tf32r(kv.y); kv.z = tf32r(kv.z); kv.w = tf32r(kv.w);
            *(float4*)(Ks + r * KSTR + c4) = kv;
            float4 vv = *(const float4*)(Vb + (size_t)(kb + r) * DINNER + c4);
            vv.x = tf32r(vv.x); vv.y = tf32r(vv.y); vv.z = tf32r(vv.z); vv.w = tf32r(vv.w);
            *(float4*)(Vs + r * VSTR + c4) = vv;
        }
        __syncthreads();

        // S = Q @ K^T  (M=16/warp, N=64 keys, K=64 dh)
        float s[8][4];
#pragma unroll
        for (int nf = 0; nf < 8; nf++)
#pragma unroll
            for (int c = 0; c < 4; c++) s[nf][c] = 0.f;
#pragma unroll
        for (int kk = 0; kk < 8; kk++) {
#pragma unroll
            for (int nf = 0; nf < 8; nf++) {
                unsigned b0 = __float_as_uint(Ks[(nf * 8 + g) * KSTR + kk * 8 + t]);
                unsigned b1 = __float_as_uint(Ks[(nf * 8 + g) * KSTR + kk * 8 + t + 4]);
                mma8(s[nf], qf[kk][0], qf[kk][1], qf[kk][2], qf[kk][3], b0, b1);
            }
        }

        // online softmax (rows g and g+8; 4 lanes per row)
        float tm0 = -1e30f, tm1 = -1e30f;
#pragma unroll
        for (int nf = 0; nf < 8; nf++) {
            tm0 = fmaxf(tm0, fmaxf(s[nf][0], s[nf][1]));
            tm1 = fmaxf(tm1, fmaxf(s[nf][2], s[nf][3]));
        }
        tm0 = fmaxf(tm0, __shfl_xor_sync(0xffffffffu, tm0, 1));
        tm0 = fmaxf(tm0, __shfl_xor_sync(0xffffffffu, tm0, 2));
        tm1 = fmaxf(tm1, __shfl_xor_sync(0xffffffffu, tm1, 1));
        tm1 = fmaxf(tm1, __shfl_xor_sync(0xffffffffu, tm1, 2));

        float nm0 = fmaxf(m0, tm0), nm1 = fmaxf(m1, tm1);
        float al0 = __expf(m0 - nm0), al1 = __expf(m1 - nm1);
        float rs0 = 0.f, rs1 = 0.f;
#pragma unroll
        for (int nf = 0; nf < 8; nf++) {
            float p0 = __expf(s[nf][0] - nm0);
            float p1 = __expf(s[nf][1] - nm0);
            float p2 = __expf(s[nf][2] - nm1);
            float p3 = __expf(s[nf][3] - nm1);
            rs0 += p0 + p1; rs1 += p2 + p3;
            int cb = nf * 8 + 2 * t;
            Pw[g * PSTR + cb]           = tf32r(p0);
            Pw[g * PSTR + cb + 1]       = tf32r(p1);
            Pw[(g + 8) * PSTR + cb]     = tf32r(p2);
            Pw[(g + 8) * PSTR + cb + 1] = tf32r(p3);
        }
        rs0 += __shfl_xor_sync(0xffffffffu, rs0, 1);
        rs0 += __shfl_xor_sync(0xffffffffu, rs0, 2);
        rs1 += __shfl_xor_sync(0xffffffffu, rs1, 1);
        rs1 += __shfl_xor_sync(0xffffffffu, rs1, 2);
        l0 = l0 * al0 + rs0;
        l1 = l1 * al1 + rs1;
        m0 = nm0; m1 = nm1;
#pragma unroll
        for (int nf = 0; nf < 8; nf++) {
            oacc[nf][0] *= al0; oacc[nf][1] *= al0;
            oacc[nf][2] *= al1; oacc[nf][3] *= al1;
        }
        __syncwarp();   // P tile visible within warp

        // O += P @ V  (M=16/warp, N=64 dh, K=64 keys)
#pragma unroll
        for (int kk = 0; kk < 8; kk++) {
            unsigned a0 = __float_as_uint(Pw[g * PSTR + kk * 8 + t]);
            unsigned a1 = __float_as_uint(Pw[(g + 8) * PSTR + kk * 8 + t]);
            unsigned a2 = __float_as_uint(Pw[g * PSTR + kk * 8 + t + 4]);
            unsigned a3 = __float_as_uint(Pw[(g + 8) * PSTR + kk * 8 + t + 4]);
#pragma unroll
            for (int nf = 0; nf < 8; nf++) {
                unsigned b0 = __float_as_uint(Vs[(kk * 8 + t) * VSTR + nf * 8 + g]);
                unsigned b1 = __float_as_uint(Vs[(kk * 8 + t + 4) * VSTR + nf * 8 + g]);
                mma8(oacc[nf], a0, a1, a2, a3, b0, b1);
            }
        }
    }

    // epilogue: divide by row sums, write [B, QL, H, DH] layout
    float inv0 = 1.0f / l0, inv1 = 1.0f / l1;
#pragma unroll
    for (int nf = 0; nf < 8; nf++) {
        int col = nf * 8 + 2 * t;
        *(float2*)(Ob + (size_t)q0 * DINNER + col) =
            make_float2(oacc[nf][0] * inv0, oacc[nf][1] * inv0);
        *(float2*)(Ob + (size_t)(q0 + 8) * DINNER + col) =
            make_float2(oacc[nf][2] * inv1, oacc[nf][3] * inv1);
    }
}

// ---------------------------------------------------------------------------
// launch
// ---------------------------------------------------------------------------
extern "C" void kernel_launch(void* const* d_in, const int* in_sizes, int n_in,
                              void* d_out, int out_size)
{
    (void)in_sizes; (void)n_in; (void)out_size;
    const float* x   = (const float*)d_in[0];
    const float* ctx = (const float*)d_in[1];
    const float* Wq  = (const float*)d_in[2];
    const float* Wk  = (const float*)d_in[3];
    const float* Wv  = (const float*)d_in[4];
    const float* Wo  = (const float*)d_in[5];
    const float* bo  = (const float*)d_in[6];
    float* out = (float*)d_out;

    float *Qb, *Kb, *Vb, *Ab;
    cudaGetSymbolAddress((void**)&Qb, g_Q);
    cudaGetSymbolAddress((void**)&Kb, g_K);
    cudaGetSymbolAddress((void**)&Vb, g_V);
    cudaGetSymbolAddress((void**)&Ab, g_A);
    cudaFuncSetAttribute(flash_attn, cudaFuncAttributeMaxDynamicSharedMemorySize,
                         ATT_SMEM);

    dim3 blk(256);
    dim3 gProj(DINNER / GBN, MROWS / GBM);   // (4, 64)

    gemm_tf32<<<gProj, blk>>>(x,   Wq, Qb, nullptr, MROWS, DINNER, SQD);
    gemm_tf32<<<gProj, blk>>>(ctx, Wk, Kb, nullptr, MROWS, DINNER, SCD);
    gemm_tf32<<<gProj, blk>>>(ctx, Wv, Vb, nullptr, MROWS, DINNER, SCD);
    flash_attn<<<dim3(SQL / 128, NHEADS, NB), blk, ATT_SMEM>>>(Qb, Kb, Vb, Ab);
    gemm_tf32<<<dim3(SQD / GBN, MROWS / GBM), blk>>>(Ab, Wo, out, bo,
                                                     MROWS, SQD, DINNER);
}

// round 2
// speedup vs baseline: 1.0043x; 1.0043x over previous
#include <cuda_runtime.h>
#include <cstdint>
#include <cstddef>

// Problem constants
#define NB      2
#define SQL     4096
#define SKL     4096
#define SQD     512
#define SCD     768
#define NHEADS  8
#define HDIM    64
#define DINNER  512
#define MROWS   (NB*SQL)   // 8192

// Scratch (allocation-free rule: __device__ globals)
__device__ float g_Q[(size_t)MROWS * DINNER];
__device__ float g_K[(size_t)MROWS * DINNER];
__device__ float g_V[(size_t)MROWS * DINNER];
__device__ float g_A[(size_t)MROWS * DINNER];

// ---------------------------------------------------------------------------
// helpers
// ---------------------------------------------------------------------------
__device__ __forceinline__ unsigned f2tf(float x) {
    unsigned u;
    asm("cvt.rna.tf32.f32 %0, %1;" : "=r"(u) : "f"(x));
    return u;
}
__device__ __forceinline__ float tf32r(float x) { return __uint_as_float(f2tf(x)); }

// D = A(16x8, tf32, row) * B(8x8, tf32, col) + C, fp32 accum
__device__ __forceinline__ void mma8(float* c,
                                     unsigned a0, unsigned a1, unsigned a2, unsigned a3,
                                     unsigned b0, unsigned b1) {
    asm volatile(
        "mma.sync.aligned.m16n8k8.row.col.f32.tf32.tf32.f32 "
        "{%0,%1,%2,%3}, {%4,%5,%6,%7}, {%8,%9}, {%0,%1,%2,%3};\n"
        : "+f"(c[0]), "+f"(c[1]), "+f"(c[2]), "+f"(c[3])
        : "r"(a0), "r"(a1), "r"(a2), "r"(a3), "r"(b0), "r"(b1));
}

// ---------------------------------------------------------------------------
// Generic TF32 GEMM: C[M,N] = A[M,K] @ B[K,N] (+bias), all fp32 row-major.
// BM=128, BN=128, BK=16, 256 threads (8 warps as 2x4), warp tile 64x32.
// Requires M%128==0, N%128==0, K%16==0 (true for all shapes here).
// ---------------------------------------------------------------------------
#define GBM 128
#define GBN 128
#define GBK 16
#define ASTR 20    // conflict-free for A-frag pattern (g*20+t distinct mod 32)
#define BSTR 136   // conflict-free for B-frag pattern (t*8+g distinct mod 32)

__global__ __launch_bounds__(256) void gemm_tf32(
    const float* __restrict__ A, const float* __restrict__ B,
    float* __restrict__ C, const float* __restrict__ bias,
    int M, int N, int K)
{
    __shared__ __align__(16) float As[GBM * ASTR];
    __shared__ __align__(16) float Bs[GBK * BSTR];

    const int tid  = threadIdx.x;
    const int warp = tid >> 5, lane = tid & 31;
    const int g = lane >> 2, t = lane & 3;
    const int wm = warp >> 2, wn = warp & 3;      // 2 x 4 warp grid
    const int mBase = blockIdx.y * GBM;
    const int nBase = blockIdx.x * GBN;

    float acc[4][4][4];
#pragma unroll
    for (int i = 0; i < 4; i++)
#pragma unroll
        for (int j = 0; j < 4; j++)
#pragma unroll
            for (int c = 0; c < 4; c++) acc[i][j][c] = 0.f;

    for (int k0 = 0; k0 < K; k0 += GBK) {
        // A tile: 128x16 = 512 float4, 2 per thread
#pragma unroll
        for (int i = 0; i < 2; i++) {
            int idx = tid + i * 256;
            int r = idx >> 2, c4 = (idx & 3) * 4;
            float4 v = *(const float4*)(A + (size_t)(mBase + r) * K + k0 + c4);
            v.x = tf32r(v.x); v.y = tf32r(v.y); v.z = tf32r(v.z); v.w = tf32r(v.w);
            *(float4*)(As + r * ASTR + c4) = v;
        }
        // B tile: 16x128 = 512 float4, 2 per thread
#pragma unroll
        for (int i = 0; i < 2; i++) {
            int idx = tid + i * 256;
            int r = idx >> 5, c4 = (idx & 31) * 4;
            float4 v = *(const float4*)(B + (size_t)(k0 + r) * N + nBase + c4);
            v.x = tf32r(v.x); v.y = tf32r(v.y); v.z = tf32r(v.z); v.w = tf32r(v.w);
            *(float4*)(Bs + r * BSTR + c4) = v;
        }
        __syncthreads();

#pragma unroll
        for (int kk = 0; kk < 2; kk++) {
            unsigned af[4][4];
#pragma unroll
            for (int mf = 0; mf < 4; mf++) {
                int rb = (wm * 64 + mf * 16 + g) * ASTR + kk * 8 + t;
                af[mf][0] = __float_as_uint(As[rb]);
                af[mf][1] = __float_as_uint(As[rb + 8 * ASTR]);
                af[mf][2] = __float_as_uint(As[rb + 4]);
                af[mf][3] = __float_as_uint(As[rb + 8 * ASTR + 4]);
            }
            unsigned bf[4][2];
#pragma unroll
            for (int nf = 0; nf < 4; nf++) {
                int cb = wn * 32 + nf * 8 + g;
                bf[nf][0] = __float_as_uint(Bs[(kk * 8 + t) * BSTR + cb]);
                bf[nf][1] = __float_as_uint(Bs[(kk * 8 + t + 4) * BSTR + cb]);
            }
#pragma unroll
            for (int mf = 0; mf < 4; mf++)
#pragma unroll
                for (int nf = 0; nf < 4; nf++)
                    mma8(acc[mf][nf], af[mf][0], af[mf][1], af[mf][2], af[mf][3],
                         bf[nf][0], bf[nf][1]);
        }
        __syncthreads();
    }

    // epilogue (+ optional bias)
#pragma unroll
    for (int mf = 0; mf < 4; mf++) {
        int r0 = mBase + wm * 64 + mf * 16 + g;
#pragma unroll
        for (int nf = 0; nf < 4; nf++) {
            int col = nBase + wn * 32 + nf * 8 + 2 * t;
            float b0 = 0.f, b1 = 0.f;
            if (bias) { b0 = bias[col]; b1 = bias[col + 1]; }
            *(float2*)(C + (size_t)r0 * N + col) =
                make_float2(acc[mf][nf][0] + b0, acc[mf][nf][1] + b1);
            *(float2*)(C + (size_t)(r0 + 8) * N + col) =
                make_float2(acc[mf][nf][2] + b0, acc[mf][nf][3] + b1);
        }
    }
}

// ---------------------------------------------------------------------------
// Flash attention, TF32 mma. One CTA = (b, h, 128 q-rows). 8 warps, each owns
// 16 q-rows (softmax fully intra-warp). KL processed in 64-key tiles.
// ---------------------------------------------------------------------------
#define KSTR 68   // Ks row stride: g*4+t distinct mod 32 -> conflict-free B-frags
#define VSTR 72   // Vs row stride: t*8+g distinct mod 32 -> conflict-free B-frags
#define PSTR 68   // Ps row stride: g*4+t distinct mod 32 -> conflict-free A-frags
#define ATT_SMEM ((64*KSTR + 64*VSTR + 8*16*PSTR) * 4)   // 70656 bytes

__global__ __launch_bounds__(256) void flash_attn(
    const float* __restrict__ Q, const float* __restrict__ Kg,
    const float* __restrict__ Vg, float* __restrict__ O)
{
    extern __shared__ __align__(16) float sm[];
    float* Ks = sm;                 // [64][KSTR]  K tile (tf32-rounded)
    float* Vs = sm + 64 * KSTR;     // [64][VSTR]  V tile
    float* Ps = Vs + 64 * VSTR;     // per-warp [16][PSTR] P tile

    const int tid  = threadIdx.x;
    const int warp = tid >> 5, lane = tid & 31;
    const int g = lane >> 2, t = lane & 3;
    const int qt = blockIdx.x, h = blockIdx.y, b = blockIdx.z;
    const float scale = 0.125f;     // 64^-0.5

    const float* Qb = Q  + (size_t)b * SQL * DINNER + h * HDIM;
    const float* Kb = Kg + (size_t)b * SKL * DINNER + h * HDIM;
    const float* Vb = Vg + (size_t)b * SKL * DINNER + h * HDIM;
    float*       Ob = O  + (size_t)b * SQL * DINNER + h * HDIM;
    float*       Pw = Ps + warp * 16 * PSTR;

    const int q0 = qt * 128 + warp * 16 + g;   // rows q0 (c0/c1) and q0+8 (c2/c3)

    // Q fragments resident in registers for the whole KL loop (scale folded in)
    unsigned qf[8][4];
#pragma unroll
    for (int kk = 0; kk < 8; kk++) {
        int c = kk * 8 + t;
        qf[kk][0] = f2tf(Qb[(size_t)q0 * DINNER + c] * scale);
        qf[kk][1] = f2tf(Qb[(size_t)(q0 + 8) * DINNER + c] * scale);
        qf[kk][2] = f2tf(Qb[(size_t)q0 * DINNER + c + 4] * scale);
        qf[kk][3] = f2tf(Qb[(size_t)(q0 + 8) * DINNER + c + 4] * scale);
    }

    float oacc[8][4];
#pragma unroll
    for (int nf = 0; nf < 8; nf++)
#pragma unroll
        for (int c = 0; c < 4; c++) oacc[nf][c] = 0.f;

    float m0 = -1e30f, m1 = -1e30f, l0 = 0.f, l1 = 0.f;

    for (int kb = 0; kb < SKL; kb += 64) {
        __syncthreads();   // previous iteration fully done with Ks/Vs
        // load K,V 64x64 tiles (tf32-rounded at store)
#pragma unroll
        for (int i = 0; i < 4; i++) {
            int idx = tid + i * 256;
            int r = idx >> 4, c4 = (idx & 15) * 4;
            float4 kv = *(const float4*)(Kb + (size_t)(kb + r) * DINNER + c4);
            kv.x = tf32r(kv.x); kv.y = tf32r(kv.y); kv.z = tf32r(kv.z); kv.w = tf32r(kv.w);
            *(float4*)(Ks + r * KSTR + c4) = kv;
            float4 vv = *(const float4*)(Vb + (size_t)(kb + r) * DINNER + c4);
            vv.x = tf32r(vv.x); vv.y = tf32r(vv.y); vv.z = tf32r(vv.z); vv.w = tf32r(vv.w);
            *(float4*)(Vs + r * VSTR + c4) = vv;
        }
        __syncthreads();

        // S = Q @ K^T  (M=16/warp, N=64 keys, K=64 dh)
        float s[8][4];
#pragma unroll
        for (int nf = 0; nf < 8; nf++)
#pragma unroll
            for (int c = 0; c < 4; c++) s[nf][c] = 0.f;
#pragma unroll
        for (int kk = 0; kk < 8; kk++) {
#pragma unroll
            for (int nf = 0; nf < 8; nf++) {
                unsigned b0 = __float_as_uint(Ks[(nf * 8 + g) * KSTR + kk * 8 + t]);
                unsigned b1 = __float_as_uint(Ks[(nf * 8 + g) * KSTR + kk * 8 + t + 4]);
                mma8(s[nf], qf[kk][0], qf[kk][1], qf[kk][2], qf[kk][3], b0, b1);
            }
        }

        // online softmax (rows g and g+8; 4 lanes per row)
        float tm0 = -1e30f, tm1 = -1e30f;
#pragma unroll
        for (int nf = 0; nf < 8; nf++) {
            tm0 = fmaxf(tm0, fmaxf(s[nf][0], s[nf][1]));
            tm1 = fmaxf(tm1, fmaxf(s[nf][2], s[nf][3]));
        }
        tm0 = fmaxf(tm0, __shfl_xor_sync(0xffffffffu, tm0, 1));
        tm0 = fmaxf(tm0, __shfl_xor_sync(0xffffffffu, tm0, 2));
        tm1 = fmaxf(tm1, __shfl_xor_sync(0xffffffffu, tm1, 1));
        tm1 = fmaxf(tm1, __shfl_xor_sync(0xffffffffu, tm1, 2));

        float nm0 = fmaxf(m0, tm0), nm1 = fmaxf(m1, tm1);
        float al0 = __expf(m0 - nm0), al1 = __expf(m1 - nm1);
        float rs0 = 0.f, rs1 = 0.f;
#pragma unroll
        for (int nf = 0; nf < 8; nf++) {
            float p0 = __expf(s[nf][0] - nm0);
            float p1 = __expf(s[nf][1] - nm0);
            float p2 = __expf(s[nf][2] - nm1);
            float p3 = __expf(s[nf][3] - nm1);
            rs0 += p0 + p1; rs1 += p2 + p3;
            int cb = nf * 8 + 2 * t;
            Pw[g * PSTR + cb]           = tf32r(p0);
            Pw[g * PSTR + cb + 1]       = tf32r(p1);
            Pw[(g + 8) * PSTR + cb]     = tf32r(p2);
            Pw[(g + 8) * PSTR + cb + 1] = tf32r(p3);
        }
        rs0 += __shfl_xor_sync(0xffffffffu, rs0, 1);
        rs0 += __shfl_xor_sync(0xffffffffu, rs0, 2);
        rs1 += __shfl_xor_sync(0xffffffffu, rs1, 1);
        rs1 += __shfl_xor_sync(0xffffffffu, rs1, 2);
        l0 = l0 * al0 + rs0;
        l1 = l1 * al1 + rs1;
        m0 = nm0; m1 = nm1;
#pragma unroll
        for (int nf = 0; nf < 8; nf++) {
            oacc[nf][0] *= al0; oacc[nf][1] *= al0;
            oacc[nf][2] *= al1; oacc[nf][3] *= al1;
        }
        __syncwarp();   // P tile visible within warp

        // O += P @ V  (M=16/warp, N=64 dh, K=64 keys)
#pragma unroll
        for (int kk = 0; kk < 8; kk++) {
            unsigned a0 = __float_as_uint(Pw[g * PSTR + kk * 8 + t]);
            unsigned a1 = __float_as_uint(Pw[(g + 8) * PSTR + kk * 8 + t]);
            unsigned a2 = __float_as_uint(Pw[g * PSTR + kk * 8 + t + 4]);
            unsigned a3 = __float_as_uint(Pw[(g + 8) * PSTR + kk * 8 + t + 4]);
#pragma unroll
            for (int nf = 0; nf < 8; nf++) {
                unsigned b0 = __float_as_uint(Vs[(kk * 8 + t) * VSTR + nf * 8 + g]);
                unsigned b1 = __float_as_uint(Vs[(kk * 8 + t + 4) * VSTR + nf * 8 + g]);
                mma8(oacc[nf], a0, a1, a2, a3, b0, b1);
            }
        }
    }

    // epilogue: divide by row sums, write [B, QL, H, DH] layout
    float inv0 = 1.0f / l0, inv1 = 1.0f / l1;
#pragma unroll
    for (int nf = 0; nf < 8; nf++) {
        int col = nf * 8 + 2 * t;
        *(float2*)(Ob + (size_t)q0 * DINNER + col) =
            make_float2(oacc[nf][0] * inv0, oacc[nf][1] * inv0);
        *(float2*)(Ob + (size_t)(q0 + 8) * DINNER + col) =
            make_float2(oacc[nf][2] * inv1, oacc[nf][3] * inv1);
    }
}

// ---------------------------------------------------------------------------
// launch
// ---------------------------------------------------------------------------
extern "C" void kernel_launch(void* const* d_in, const int* in_sizes, int n_in,
                              void* d_out, int out_size)
{
    (void)in_sizes; (void)n_in; (void)out_size;
    const float* x   = (const float*)d_in[0];
    const float* ctx = (const float*)d_in[1];
    const float* Wq  = (const float*)d_in[2];
    const float* Wk  = (const float*)d_in[3];
    const float* Wv  = (const float*)d_in[4];
    const float* Wo  = (const float*)d_in[5];
    const float* bo  = (const float*)d_in[6];
    float* out = (float*)d_out;

    float *Qb, *Kb, *Vb, *Ab;
    cudaGetSymbolAddress((void**)&Qb, g_Q);
    cudaGetSymbolAddress((void**)&Kb, g_K);
    cudaGetSymbolAddress((void**)&Vb, g_V);
    cudaGetSymbolAddress((void**)&Ab, g_A);
    cudaFuncSetAttribute(flash_attn, cudaFuncAttributeMaxDynamicSharedMemorySize,
                         ATT_SMEM);

    dim3 blk(256);
    dim3 gProj(DINNER / GBN, MROWS / GBM);   // (4, 64)

    gemm_tf32<<<gProj, blk>>>(x,   Wq, Qb, nullptr, MROWS, DINNER, SQD);
    gemm_tf32<<<gProj, blk>>>(ctx, Wk, Kb, nullptr, MROWS, DINNER, SCD);
    gemm_tf32<<<gProj, blk>>>(ctx, Wv, Vb, nullptr, MROWS, DINNER, SCD);
    flash_attn<<<dim3(SQL / 128, NHEADS, NB), blk, ATT_SMEM>>>(Qb, Kb, Vb, Ab);
    gemm_tf32<<<dim3(SQD / GBN, MROWS / GBM), blk>>>(Ab, Wo, out, bo,
                                                     MROWS, SQD, DINNER);
}

// round 3
// speedup vs baseline: 1.1384x; 1.1335x over previous
#include <cuda_runtime.h>
#include <cstdint>
#include <cstddef>

// Problem constants
#define NB      2
#define SQL     4096
#define SKL     4096
#define SQD     512
#define SCD     768
#define NHEADS  8
#define HDIM    64
#define DINNER  512
#define MROWS   (NB*SQL)   // 8192

// Scratch (allocation-free rule: __device__ globals)
__device__ float g_Q[(size_t)MROWS * DINNER];
__device__ float g_K[(size_t)MROWS * DINNER];
__device__ float g_V[(size_t)MROWS * DINNER];
__device__ float g_A[(size_t)MROWS * DINNER];

// ---------------------------------------------------------------------------
// helpers
// ---------------------------------------------------------------------------
__device__ __forceinline__ unsigned f2tf(float x) {
    unsigned u;
    asm("cvt.rna.tf32.f32 %0, %1;" : "=r"(u) : "f"(x));
    return u;
}
__device__ __forceinline__ float tf32r(float x) { return __uint_as_float(f2tf(x)); }

// D = A(16x8, tf32, row) * B(8x8, tf32, col) + C, fp32 accum
__device__ __forceinline__ void mma8(float* c,
                                     unsigned a0, unsigned a1, unsigned a2, unsigned a3,
                                     unsigned b0, unsigned b1) {
    asm volatile(
        "mma.sync.aligned.m16n8k8.row.col.f32.tf32.tf32.f32 "
        "{%0,%1,%2,%3}, {%4,%5,%6,%7}, {%8,%9}, {%0,%1,%2,%3};\n"
        : "+f"(c[0]), "+f"(c[1]), "+f"(c[2]), "+f"(c[3])
        : "r"(a0), "r"(a1), "r"(a2), "r"(a3), "r"(b0), "r"(b1));
}

// ---------------------------------------------------------------------------
// Generic TF32 GEMM: C[M,N] = A[M,K] @ B[K,N] (+bias), all fp32 row-major.
// BM=128, BN=128, BK=16, 256 threads (8 warps as 2x4), warp tile 64x32.
// ---------------------------------------------------------------------------
#define GBM 128
#define GBN 128
#define GBK 16
#define ASTR 20    // conflict-free for A-frag pattern
#define BSTR 136   // conflict-free for B-frag pattern

__global__ __launch_bounds__(256, 2) void gemm_tf32(
    const float* __restrict__ A, const float* __restrict__ B,
    float* __restrict__ C, const float* __restrict__ bias,
    int M, int N, int K)
{
    __shared__ __align__(16) float As[GBM * ASTR];
    __shared__ __align__(16) float Bs[GBK * BSTR];

    const int tid  = threadIdx.x;
    const int warp = tid >> 5, lane = tid & 31;
    const int g = lane >> 2, t = lane & 3;
    const int wm = warp >> 2, wn = warp & 3;      // 2 x 4 warp grid
    const int mBase = blockIdx.y * GBM;
    const int nBase = blockIdx.x * GBN;

    float acc[4][4][4];
#pragma unroll
    for (int i = 0; i < 4; i++)
#pragma unroll
        for (int j = 0; j < 4; j++)
#pragma unroll
            for (int c = 0; c < 4; c++) acc[i][j][c] = 0.f;

#pragma unroll 1
    for (int k0 = 0; k0 < K; k0 += GBK) {
        // A tile: 128x16 = 512 float4, 2 per thread
#pragma unroll
        for (int i = 0; i < 2; i++) {
            int idx = tid + i * 256;
            int r = idx >> 2, c4 = (idx & 3) * 4;
            float4 v = *(const float4*)(A + (size_t)(mBase + r) * K + k0 + c4);
            v.x = tf32r(v.x); v.y = tf32r(v.y); v.z = tf32r(v.z); v.w = tf32r(v.w);
            *(float4*)(As + r * ASTR + c4) = v;
        }
        // B tile: 16x128 = 512 float4, 2 per thread
#pragma unroll
        for (int i = 0; i < 2; i++) {
            int idx = tid + i * 256;
            int r = idx >> 5, c4 = (idx & 31) * 4;
            float4 v = *(const float4*)(B + (size_t)(k0 + r) * N + nBase + c4);
            v.x = tf32r(v.x); v.y = tf32r(v.y); v.z = tf32r(v.z); v.w = tf32r(v.w);
            *(float4*)(Bs + r * BSTR + c4) = v;
        }
        __syncthreads();

#pragma unroll
        for (int kk = 0; kk < 2; kk++) {
            unsigned af[4][4];
#pragma unroll
            for (int mf = 0; mf < 4; mf++) {
                int rb = (wm * 64 + mf * 16 + g) * ASTR + kk * 8 + t;
                af[mf][0] = __float_as_uint(As[rb]);
                af[mf][1] = __float_as_uint(As[rb + 8 * ASTR]);
                af[mf][2] = __float_as_uint(As[rb + 4]);
                af[mf][3] = __float_as_uint(As[rb + 8 * ASTR + 4]);
            }
            unsigned bf[4][2];
#pragma unroll
            for (int nf = 0; nf < 4; nf++) {
                int cb = wn * 32 + nf * 8 + g;
                bf[nf][0] = __float_as_uint(Bs[(kk * 8 + t) * BSTR + cb]);
                bf[nf][1] = __float_as_uint(Bs[(kk * 8 + t + 4) * BSTR + cb]);
            }
#pragma unroll
            for (int mf = 0; mf < 4; mf++)
#pragma unroll
                for (int nf = 0; nf < 4; nf++)
                    mma8(acc[mf][nf], af[mf][0], af[mf][1], af[mf][2], af[mf][3],
                         bf[nf][0], bf[nf][1]);
        }
        __syncthreads();
    }

    // epilogue (+ optional bias)
#pragma unroll
    for (int mf = 0; mf < 4; mf++) {
        int r0 = mBase + wm * 64 + mf * 16 + g;
#pragma unroll
        for (int nf = 0; nf < 4; nf++) {
            int col = nBase + wn * 32 + nf * 8 + 2 * t;
            float b0 = 0.f, b1 = 0.f;
            if (bias) { b0 = bias[col]; b1 = bias[col + 1]; }
            *(float2*)(C + (size_t)r0 * N + col) =
                make_float2(acc[mf][nf][0] + b0, acc[mf][nf][1] + b1);
            *(float2*)(C + (size_t)(r0 + 8) * N + col) =
                make_float2(acc[mf][nf][2] + b0, acc[mf][nf][3] + b1);
        }
    }
}

// ---------------------------------------------------------------------------
// Flash attention, TF32 mma. One CTA = (b, h, 128 q-rows). 8 warps, each owns
// 16 q-rows (softmax fully intra-warp). KL processed in 64-key tiles.
// 2 CTAs/SM target (regs capped at 128).
// ---------------------------------------------------------------------------
#define KSTR 68   // Ks row stride: conflict-free B-frags
#define VSTR 72   // Vs row stride: conflict-free B-frags
#define PSTR 68   // Ps row stride: conflict-free A-frags
#define ATT_SMEM ((64*KSTR + 64*VSTR + 8*16*PSTR) * 4)   // 70656 bytes

__global__ __launch_bounds__(256, 2) void flash_attn(
    const float* __restrict__ Q, const float* __restrict__ Kg,
    const float* __restrict__ Vg, float* __restrict__ O)
{
    extern __shared__ __align__(16) float sm[];
    float* Ks = sm;                 // [64][KSTR]  K tile (tf32-rounded)
    float* Vs = sm + 64 * KSTR;     // [64][VSTR]  V tile
    float* Ps = Vs + 64 * VSTR;     // per-warp [16][PSTR] P tile

    const int tid  = threadIdx.x;
    const int warp = tid >> 5, lane = tid & 31;
    const int g = lane >> 2, t = lane & 3;
    const int qt = blockIdx.x, h = blockIdx.y, b = blockIdx.z;
    const float scale = 0.125f;     // 64^-0.5

    const float* Qb = Q  + (size_t)b * SQL * DINNER + h * HDIM;
    const float* Kb = Kg + (size_t)b * SKL * DINNER + h * HDIM;
    const float* Vb = Vg + (size_t)b * SKL * DINNER + h * HDIM;
    float*       Ob = O  + (size_t)b * SQL * DINNER + h * HDIM;
    float*       Pw = Ps + warp * 16 * PSTR;

    const int q0 = qt * 128 + warp * 16 + g;   // rows q0 (c0/c1) and q0+8 (c2/c3)

    // Q fragments resident in registers for the whole KL loop (scale folded in)
    unsigned qf[8][4];
#pragma unroll
    for (int kk = 0; kk < 8; kk++) {
        int c = kk * 8 + t;
        qf[kk][0] = f2tf(Qb[(size_t)q0 * DINNER + c] * scale);
        qf[kk][1] = f2tf(Qb[(size_t)(q0 + 8) * DINNER + c] * scale);
        qf[kk][2] = f2tf(Qb[(size_t)q0 * DINNER + c + 4] * scale);
        qf[kk][3] = f2tf(Qb[(size_t)(q0 + 8) * DINNER + c + 4] * scale);
    }

    float oacc[8][4];
#pragma unroll
    for (int nf = 0; nf < 8; nf++)
#pragma unroll
        for (int c = 0; c < 4; c++) oacc[nf][c] = 0.f;

    float m0 = -1e30f, m1 = -1e30f, l0 = 0.f, l1 = 0.f;

#pragma unroll 1
    for (int kb = 0; kb < SKL; kb += 64) {
        __syncthreads();   // previous iteration fully done with Ks/Vs
        // load K,V 64x64 tiles (tf32-rounded at store)
#pragma unroll
        for (int i = 0; i < 4; i++) {
            int idx = tid + i * 256;
            int r = idx >> 4, c4 = (idx & 15) * 4;
            float4 kv = *(const float4*)(Kb + (size_t)(kb + r) * DINNER + c4);
            kv.x = tf32r(kv.x); kv.y = tf32r(kv.y); kv.z = tf32r(kv.z); kv.w = tf32r(kv.w);
            *(float4*)(Ks + r * KSTR + c4) = kv;
            float4 vv = *(const float4*)(Vb + (size_t)(kb + r) * DINNER + c4);
            vv.x = tf32r(vv.x); vv.y = tf32r(vv.y); vv.z = tf32r(vv.z); vv.w = tf32r(vv.w);
            *(float4*)(Vs + r * VSTR + c4) = vv;
        }
        __syncthreads();

        // S = Q @ K^T  (M=16/warp, N=64 keys, K=64 dh)
        float s[8][4];
#pragma unroll
        for (int nf = 0; nf < 8; nf++)
#pragma unroll
            for (int c = 0; c < 4; c++) s[nf][c] = 0.f;
#pragma unroll
        for (int kk = 0; kk < 8; kk++) {
#pragma unroll
            for (int nf = 0; nf < 8; nf++) {
                unsigned b0 = __float_as_uint(Ks[(nf * 8 + g) * KSTR + kk * 8 + t]);
                unsigned b1 = __float_as_uint(Ks[(nf * 8 + g) * KSTR + kk * 8 + t + 4]);
                mma8(s[nf], qf[kk][0], qf[kk][1], qf[kk][2], qf[kk][3], b0, b1);
            }
        }

        // online softmax (rows g and g+8; 4 lanes per row)
        float tm0 = -1e30f, tm1 = -1e30f;
#pragma unroll
        for (int nf = 0; nf < 8; nf++) {
            tm0 = fmaxf(tm0, fmaxf(s[nf][0], s[nf][1]));
            tm1 = fmaxf(tm1, fmaxf(s[nf][2], s[nf][3]));
        }
        tm0 = fmaxf(tm0, __shfl_xor_sync(0xffffffffu, tm0, 1));
        tm0 = fmaxf(tm0, __shfl_xor_sync(0xffffffffu, tm0, 2));
        tm1 = fmaxf(tm1, __shfl_xor_sync(0xffffffffu, tm1, 1));
        tm1 = fmaxf(tm1, __shfl_xor_sync(0xffffffffu, tm1, 2));

        float nm0 = fmaxf(m0, tm0), nm1 = fmaxf(m1, tm1);
        float al0 = __expf(m0 - nm0), al1 = __expf(m1 - nm1);
        float rs0 = 0.f, rs1 = 0.f;
#pragma unroll
        for (int nf = 0; nf < 8; nf++) {
            float p0 = __expf(s[nf][0] - nm0);
            float p1 = __expf(s[nf][1] - nm0);
            float p2 = __expf(s[nf][2] - nm1);
            float p3 = __expf(s[nf][3] - nm1);
            rs0 += p0 + p1; rs1 += p2 + p3;
            int cb = nf * 8 + 2 * t;
            *(float2*)(Pw + g * PSTR + cb)       = make_float2(tf32r(p0), tf32r(p1));
            *(float2*)(Pw + (g + 8) * PSTR + cb) = make_float2(tf32r(p2), tf32r(p3));
        }
        rs0 += __shfl_xor_sync(0xffffffffu, rs0, 1);
        rs0 += __shfl_xor_sync(0xffffffffu, rs0, 2);
        rs1 += __shfl_xor_sync(0xffffffffu, rs1, 1);
        rs1 += __shfl_xor_sync(0xffffffffu, rs1, 2);
        l0 = l0 * al0 + rs0;
        l1 = l1 * al1 + rs1;
        m0 = nm0; m1 = nm1;
#pragma unroll
        for (int nf = 0; nf < 8; nf++) {
            oacc[nf][0] *= al0; oacc[nf][1] *= al0;
            oacc[nf][2] *= al1; oacc[nf][3] *= al1;
        }
        __syncwarp();   // P tile visible within warp

        // O += P @ V  (M=16/warp, N=64 dh, K=64 keys)
#pragma unroll
        for (int kk = 0; kk < 8; kk++) {
            unsigned a0 = __float_as_uint(Pw[g * PSTR + kk * 8 + t]);
            unsigned a1 = __float_as_uint(Pw[(g + 8) * PSTR + kk * 8 + t]);
            unsigned a2 = __float_as_uint(Pw[g * PSTR + kk * 8 + t + 4]);
            unsigned a3 = __float_as_uint(Pw[(g + 8) * PSTR + kk * 8 + t + 4]);
#pragma unroll
            for (int nf = 0; nf < 8; nf++) {
                unsigned b0 = __float_as_uint(Vs[(kk * 8 + t) * VSTR + nf * 8 + g]);
                unsigned b1 = __float_as_uint(Vs[(kk * 8 + t + 4) * VSTR + nf * 8 + g]);
                mma8(oacc[nf], a0, a1, a2, a3, b0, b1);
            }
        }
    }

    // epilogue: divide by row sums, write [B, QL, H, DH] layout
    float inv0 = 1.0f / l0, inv1 = 1.0f / l1;
#pragma unroll
    for (int nf = 0; nf < 8; nf++) {
        int col = nf * 8 + 2 * t;
        *(float2*)(Ob + (size_t)q0 * DINNER + col) =
            make_float2(oacc[nf][0] * inv0, oacc[nf][1] * inv0);
        *(float2*)(Ob + (size_t)(q0 + 8) * DINNER + col) =
            make_float2(oacc[nf][2] * inv1, oacc[nf][3] * inv1);
    }
}

// ---------------------------------------------------------------------------
// launch
// ---------------------------------------------------------------------------
extern "C" void kernel_launch(void* const* d_in, const int* in_sizes, int n_in,
                              void* d_out, int out_size)
{
    (void)in_sizes; (void)n_in; (void)out_size;
    const float* x   = (const float*)d_in[0];
    const float* ctx = (const float*)d_in[1];
    const float* Wq  = (const float*)d_in[2];
    const float* Wk  = (const float*)d_in[3];
    const float* Wv  = (const float*)d_in[4];
    const float* Wo  = (const float*)d_in[5];
    const float* bo  = (const float*)d_in[6];
    float* out = (float*)d_out;

    float *Qb, *Kb, *Vb, *Ab;
    cudaGetSymbolAddress((void**)&Qb, g_Q);
    cudaGetSymbolAddress((void**)&Kb, g_K);
    cudaGetSymbolAddress((void**)&Vb, g_V);
    cudaGetSymbolAddress((void**)&Ab, g_A);
    cudaFuncSetAttribute(flash_attn, cudaFuncAttributeMaxDynamicSharedMemorySize,
                         ATT_SMEM);

    dim3 blk(256);
    dim3 gProj(DINNER / GBN, MROWS / GBM);   // (4, 64)

    gemm_tf32<<<gProj, blk>>>(x,   Wq, Qb, nullptr, MROWS, DINNER, SQD);
    gemm_tf32<<<gProj, blk>>>(ctx, Wk, Kb, nullptr, MROWS, DINNER, SCD);
    gemm_tf32<<<gProj, blk>>>(ctx, Wv, Vb, nullptr, MROWS, DINNER, SCD);
    flash_attn<<<dim3(SQL / 128, NHEADS, NB), blk, ATT_SMEM>>>(Qb, Kb, Vb, Ab);
    gemm_tf32<<<dim3(SQD / GBN, MROWS / GBM), blk>>>(Ab, Wo, out, bo,
                                                     MROWS, SQD, DINNER);
}

// round 4
// speedup vs baseline: 1.2958x; 1.1382x over previous
#include <cuda_runtime.h>
#include <cstdint>
#include <cstddef>

// Problem constants
#define NB      2
#define SQL     4096
#define SKL     4096
#define SQD     512
#define SCD     768
#define NHEADS  8
#define HDIM    64
#define DINNER  512
#define MROWS   (NB*SQL)   // 8192

// Scratch (allocation-free rule: __device__ globals)
__device__ float g_Q[(size_t)MROWS * DINNER];
__device__ float g_K[(size_t)MROWS * DINNER];
__device__ float g_V[(size_t)MROWS * DINNER];
__device__ float g_A[(size_t)MROWS * DINNER];

// ---------------------------------------------------------------------------
// helpers
// ---------------------------------------------------------------------------
__device__ __forceinline__ unsigned f2tf(float x) {
    unsigned u;
    asm("cvt.rna.tf32.f32 %0, %1;" : "=r"(u) : "f"(x));
    return u;
}
__device__ __forceinline__ float tf32r(float x) { return __uint_as_float(f2tf(x)); }

__device__ __forceinline__ float ex2(float x) {
    float r;
    asm("ex2.approx.ftz.f32 %0, %1;" : "=f"(r) : "f"(x));
    return r;
}

// D = A(16x8, tf32, row) * B(8x8, tf32, col) + C, fp32 accum
__device__ __forceinline__ void mma8(float* c,
                                     unsigned a0, unsigned a1, unsigned a2, unsigned a3,
                                     unsigned b0, unsigned b1) {
    asm volatile(
        "mma.sync.aligned.m16n8k8.row.col.f32.tf32.tf32.f32 "
        "{%0,%1,%2,%3}, {%4,%5,%6,%7}, {%8,%9}, {%0,%1,%2,%3};\n"
        : "+f"(c[0]), "+f"(c[1]), "+f"(c[2]), "+f"(c[3])
        : "r"(a0), "r"(a1), "r"(a2), "r"(a3), "r"(b0), "r"(b1));
}

// ---------------------------------------------------------------------------
// Generic TF32 GEMM: C[M,N] = A[M,K] @ B[K,N] (+bias), all fp32 row-major.
// BM=128, BN=128, BK=16, 256 threads (8 warps as 2x4), warp tile 64x32.
// ---------------------------------------------------------------------------
#define GBM 128
#define GBN 128
#define GBK 16
#define ASTR 20
#define BSTR 136

__global__ __launch_bounds__(256, 2) void gemm_tf32(
    const float* __restrict__ A, const float* __restrict__ B,
    float* __restrict__ C, const float* __restrict__ bias,
    int M, int N, int K)
{
    __shared__ __align__(16) float As[GBM * ASTR];
    __shared__ __align__(16) float Bs[GBK * BSTR];

    const int tid  = threadIdx.x;
    const int warp = tid >> 5, lane = tid & 31;
    const int g = lane >> 2, t = lane & 3;
    const int wm = warp >> 2, wn = warp & 3;
    const int mBase = blockIdx.y * GBM;
    const int nBase = blockIdx.x * GBN;

    float acc[4][4][4];
#pragma unroll
    for (int i = 0; i < 4; i++)
#pragma unroll
        for (int j = 0; j < 4; j++)
#pragma unroll
            for (int c = 0; c < 4; c++) acc[i][j][c] = 0.f;

#pragma unroll 1
    for (int k0 = 0; k0 < K; k0 += GBK) {
#pragma unroll
        for (int i = 0; i < 2; i++) {
            int idx = tid + i * 256;
            int r = idx >> 2, c4 = (idx & 3) * 4;
            float4 v = *(const float4*)(A + (size_t)(mBase + r) * K + k0 + c4);
            v.x = tf32r(v.x); v.y = tf32r(v.y); v.z = tf32r(v.z); v.w = tf32r(v.w);
            *(float4*)(As + r * ASTR + c4) = v;
        }
#pragma unroll
        for (int i = 0; i < 2; i++) {
            int idx = tid + i * 256;
            int r = idx >> 5, c4 = (idx & 31) * 4;
            float4 v = *(const float4*)(B + (size_t)(k0 + r) * N + nBase + c4);
            v.x = tf32r(v.x); v.y = tf32r(v.y); v.z = tf32r(v.z); v.w = tf32r(v.w);
            *(float4*)(Bs + r * BSTR + c4) = v;
        }
        __syncthreads();

#pragma unroll
        for (int kk = 0; kk < 2; kk++) {
            unsigned af[4][4];
#pragma unroll
            for (int mf = 0; mf < 4; mf++) {
                int rb = (wm * 64 + mf * 16 + g) * ASTR + kk * 8 + t;
                af[mf][0] = __float_as_uint(As[rb]);
                af[mf][1] = __float_as_uint(As[rb + 8 * ASTR]);
                af[mf][2] = __float_as_uint(As[rb + 4]);
                af[mf][3] = __float_as_uint(As[rb + 8 * ASTR + 4]);
            }
            unsigned bf[4][2];
#pragma unroll
            for (int nf = 0; nf < 4; nf++) {
                int cb = wn * 32 + nf * 8 + g;
                bf[nf][0] = __float_as_uint(Bs[(kk * 8 + t) * BSTR + cb]);
                bf[nf][1] = __float_as_uint(Bs[(kk * 8 + t + 4) * BSTR + cb]);
            }
#pragma unroll
            for (int mf = 0; mf < 4; mf++)
#pragma unroll
                for (int nf = 0; nf < 4; nf++)
                    mma8(acc[mf][nf], af[mf][0], af[mf][1], af[mf][2], af[mf][3],
                         bf[nf][0], bf[nf][1]);
        }
        __syncthreads();
    }

#pragma unroll
    for (int mf = 0; mf < 4; mf++) {
        int r0 = mBase + wm * 64 + mf * 16 + g;
#pragma unroll
        for (int nf = 0; nf < 4; nf++) {
            int col = nBase + wn * 32 + nf * 8 + 2 * t;
            float b0 = 0.f, b1 = 0.f;
            if (bias) { b0 = bias[col]; b1 = bias[col + 1]; }
            *(float2*)(C + (size_t)r0 * N + col) =
                make_float2(acc[mf][nf][0] + b0, acc[mf][nf][1] + b1);
            *(float2*)(C + (size_t)(r0 + 8) * N + col) =
                make_float2(acc[mf][nf][2] + b0, acc[mf][nf][3] + b1);
        }
    }
}

// ---------------------------------------------------------------------------
// Flash attention v2: one CTA = (b, h, 256 q-rows), 8 warps, M=32 rows/warp
// (two m16 tiles at +0 and +16). KV processed in 32-key tiles, double-buffered
// smem with register prefetch. Softmax in log2 domain (ex2).
// ---------------------------------------------------------------------------
#define TKEY 32
#define NT   (SKL / TKEY)          // 128 tiles
#define KSTR 68                    // 64-col K tile rows, conflict-free B-frags
#define VSTR 72                    // 64-col V tile rows, conflict-free B-frags
#define PSTR 36                    // 32-col P tile rows, conflict-free A-frags
#define KBUF (TKEY * KSTR)         // 2176 floats
#define VBUF (TKEY * VSTR)         // 2304 floats
#define ATT_SMEM ((2 * (KBUF + VBUF) + 8 * 32 * PSTR) * 4)   // 72704 bytes

__global__ __launch_bounds__(256) void flash_attn(
    const float* __restrict__ Q, const float* __restrict__ Kg,
    const float* __restrict__ Vg, float* __restrict__ O)
{
    extern __shared__ __align__(16) float sm[];
    // layout: Ks0, Vs0, Ks1, Vs1, P
    float* Ps = sm + 2 * (KBUF + VBUF);

    const int tid  = threadIdx.x;
    const int warp = tid >> 5, lane = tid & 31;
    const int g = lane >> 2, t = lane & 3;
    const int h = blockIdx.y, b = blockIdx.z;
    // scale * log2(e): softmax done in base-2
    const float scale = 0.125f * 1.44269504088896340736f;

    const float* Qb = Q  + (size_t)b * SQL * DINNER + h * HDIM;
    const float* Kb = Kg + (size_t)b * SKL * DINNER + h * HDIM;
    const float* Vb = Vg + (size_t)b * SKL * DINNER + h * HDIM;
    float*       Ob = O  + (size_t)b * SQL * DINNER + h * HDIM;
    float*       Pw = Ps + warp * 32 * PSTR;

    const int q0 = blockIdx.x * 256 + warp * 32 + g;  // rows q0,+8,+16,+24

    // Q fragments for M=32 (two m16 tiles), scale folded, tf32-rounded.
    unsigned qf[8][8];
#pragma unroll
    for (int kk = 0; kk < 8; kk++) {
        int c = kk * 8 + t;
#pragma unroll
        for (int half = 0; half < 2; half++) {
            int r = q0 + half * 16;
            qf[kk][half * 4 + 0] = f2tf(Qb[(size_t)r * DINNER + c] * scale);
            qf[kk][half * 4 + 1] = f2tf(Qb[(size_t)(r + 8) * DINNER + c] * scale);
            qf[kk][half * 4 + 2] = f2tf(Qb[(size_t)r * DINNER + c + 4] * scale);
            qf[kk][half * 4 + 3] = f2tf(Qb[(size_t)(r + 8) * DINNER + c + 4] * scale);
        }
    }

    float oacc[8][8];
#pragma unroll
    for (int nf = 0; nf < 8; nf++)
#pragma unroll
        for (int c = 0; c < 8; c++) oacc[nf][c] = 0.f;

    float mrow[4], lrow[4];
#pragma unroll
    for (int r = 0; r < 4; r++) { mrow[r] = -1e30f; lrow[r] = 0.f; }

    // staging indices: 512 float4 per 32x64 tile, 2 per thread
    const int sr0 = tid >> 4,          sc0 = (tid & 15) * 4;
    const int sr1 = (tid + 256) >> 4,  sc1 = (tid & 15) * 4;

    // preload tile 0
    {
        float4 k0 = *(const float4*)(Kb + (size_t)sr0 * DINNER + sc0);
        float4 k1 = *(const float4*)(Kb + (size_t)sr1 * DINNER + sc1);
        float4 v0 = *(const float4*)(Vb + (size_t)sr0 * DINNER + sc0);
        float4 v1 = *(const float4*)(Vb + (size_t)sr1 * DINNER + sc1);
        k0.x=tf32r(k0.x); k0.y=tf32r(k0.y); k0.z=tf32r(k0.z); k0.w=tf32r(k0.w);
        k1.x=tf32r(k1.x); k1.y=tf32r(k1.y); k1.z=tf32r(k1.z); k1.w=tf32r(k1.w);
        v0.x=tf32r(v0.x); v0.y=tf32r(v0.y); v0.z=tf32r(v0.z); v0.w=tf32r(v0.w);
        v1.x=tf32r(v1.x); v1.y=tf32r(v1.y); v1.z=tf32r(v1.z); v1.w=tf32r(v1.w);
        *(float4*)(sm + sr0 * KSTR + sc0) = k0;
        *(float4*)(sm + sr1 * KSTR + sc1) = k1;
        *(float4*)(sm + KBUF + sr0 * VSTR + sc0) = v0;
        *(float4*)(sm + KBUF + sr1 * VSTR + sc1) = v1;
    }
    __syncthreads();

#pragma unroll 1
    for (int it = 0; it < NT; it++) {
        // prefetch next tile into registers
        float4 pk0, pk1, pv0, pv1;
        const bool more = (it + 1 < NT);
        if (more) {
            const float* Kn = Kb + (size_t)(it + 1) * TKEY * DINNER;
            const float* Vn = Vb + (size_t)(it + 1) * TKEY * DINNER;
            pk0 = *(const float4*)(Kn + (size_t)sr0 * DINNER + sc0);
            pk1 = *(const float4*)(Kn + (size_t)sr1 * DINNER + sc1);
            pv0 = *(const float4*)(Vn + (size_t)sr0 * DINNER + sc0);
            pv1 = *(const float4*)(Vn + (size_t)sr1 * DINNER + sc1);
        }

        float* Ks = sm + (it & 1) * (KBUF + VBUF);
        float* Vs = Ks + KBUF;

        // S = Q @ K^T : M=32 (2 m16), N=32 keys (4 n8 groups), K=64 dh
        float s[4][8];
#pragma unroll
        for (int nf = 0; nf < 4; nf++)
#pragma unroll
            for (int c = 0; c < 8; c++) s[nf][c] = 0.f;
#pragma unroll
        for (int kk = 0; kk < 8; kk++) {
#pragma unroll
            for (int nf = 0; nf < 4; nf++) {
                unsigned b0 = __float_as_uint(Ks[(nf * 8 + g) * KSTR + kk * 8 + t]);
                unsigned b1 = __float_as_uint(Ks[(nf * 8 + g) * KSTR + kk * 8 + t + 4]);
                mma8(&s[nf][0], qf[kk][0], qf[kk][1], qf[kk][2], qf[kk][3], b0, b1);
                mma8(&s[nf][4], qf[kk][4], qf[kk][5], qf[kk][6], qf[kk][7], b0, b1);
            }
        }

        // online softmax over 4 row-groups (rows q0, q0+8, q0+16, q0+24)
        float tm[4];
#pragma unroll
        for (int r = 0; r < 4; r++) tm[r] = -1e30f;
#pragma unroll
        for (int nf = 0; nf < 4; nf++) {
            tm[0] = fmaxf(tm[0], fmaxf(s[nf][0], s[nf][1]));
            tm[1] = fmaxf(tm[1], fmaxf(s[nf][2], s[nf][3]));
            tm[2] = fmaxf(tm[2], fmaxf(s[nf][4], s[nf][5]));
            tm[3] = fmaxf(tm[3], fmaxf(s[nf][6], s[nf][7]));
        }
#pragma unroll
        for (int r = 0; r < 4; r++) {
            tm[r] = fmaxf(tm[r], __shfl_xor_sync(0xffffffffu, tm[r], 1));
            tm[r] = fmaxf(tm[r], __shfl_xor_sync(0xffffffffu, tm[r], 2));
        }
        float nm[4], al[4], rs[4];
#pragma unroll
        for (int r = 0; r < 4; r++) {
            nm[r] = fmaxf(mrow[r], tm[r]);
            al[r] = ex2(mrow[r] - nm[r]);
            rs[r] = 0.f;
        }
#pragma unroll
        for (int nf = 0; nf < 4; nf++) {
            float p0 = ex2(s[nf][0] - nm[0]);
            float p1 = ex2(s[nf][1] - nm[0]);
            float p2 = ex2(s[nf][2] - nm[1]);
            float p3 = ex2(s[nf][3] - nm[1]);
            float p4 = ex2(s[nf][4] - nm[2]);
            float p5 = ex2(s[nf][5] - nm[2]);
            float p6 = ex2(s[nf][6] - nm[3]);
            float p7 = ex2(s[nf][7] - nm[3]);
            rs[0] += p0 + p1; rs[1] += p2 + p3;
            rs[2] += p4 + p5; rs[3] += p6 + p7;
            int cb = nf * 8 + 2 * t;
            *(float2*)(Pw + g * PSTR + cb)        = make_float2(tf32r(p0), tf32r(p1));
            *(float2*)(Pw + (g + 8) * PSTR + cb)  = make_float2(tf32r(p2), tf32r(p3));
            *(float2*)(Pw + (g + 16) * PSTR + cb) = make_float2(tf32r(p4), tf32r(p5));
            *(float2*)(Pw + (g + 24) * PSTR + cb) = make_float2(tf32r(p6), tf32r(p7));
        }
#pragma unroll
        for (int r = 0; r < 4; r++) {
            rs[r] += __shfl_xor_sync(0xffffffffu, rs[r], 1);
            rs[r] += __shfl_xor_sync(0xffffffffu, rs[r], 2);
            lrow[r] = lrow[r] * al[r] + rs[r];
            mrow[r] = nm[r];
        }
#pragma unroll
        for (int nf = 0; nf < 8; nf++) {
            oacc[nf][0] *= al[0]; oacc[nf][1] *= al[0];
            oacc[nf][2] *= al[1]; oacc[nf][3] *= al[1];
            oacc[nf][4] *= al[2]; oacc[nf][5] *= al[2];
            oacc[nf][6] *= al[3]; oacc[nf][7] *= al[3];
        }
        __syncwarp();   // P tile visible within warp

        // O += P @ V : M=32, N=64 dh, K=32 keys (4 k8 groups)
#pragma unroll
        for (int kk = 0; kk < 4; kk++) {
            unsigned a0 = __float_as_uint(Pw[g * PSTR + kk * 8 + t]);
            unsigned a1 = __float_as_uint(Pw[(g + 8) * PSTR + kk * 8 + t]);
            unsigned a2 = __float_as_uint(Pw[g * PSTR + kk * 8 + t + 4]);
            unsigned a3 = __float_as_uint(Pw[(g + 8) * PSTR + kk * 8 + t + 4]);
            unsigned a4 = __float_as_uint(Pw[(g + 16) * PSTR + kk * 8 + t]);
            unsigned a5 = __float_as_uint(Pw[(g + 24) * PSTR + kk * 8 + t]);
            unsigned a6 = __float_as_uint(Pw[(g + 16) * PSTR + kk * 8 + t + 4]);
            unsigned a7 = __float_as_uint(Pw[(g + 24) * PSTR + kk * 8 + t + 4]);
#pragma unroll
            for (int nf = 0; nf < 8; nf++) {
                unsigned b0 = __float_as_uint(Vs[(kk * 8 + t) * VSTR + nf * 8 + g]);
                unsigned b1 = __float_as_uint(Vs[(kk * 8 + t + 4) * VSTR + nf * 8 + g]);
                mma8(&oacc[nf][0], a0, a1, a2, a3, b0, b1);
                mma8(&oacc[nf][4], a4, a5, a6, a7, b0, b1);
            }
        }

        // stage prefetched tile into the other buffer
        if (more) {
            float* Kd = sm + ((it + 1) & 1) * (KBUF + VBUF);
            float* Vd = Kd + KBUF;
            pk0.x=tf32r(pk0.x); pk0.y=tf32r(pk0.y); pk0.z=tf32r(pk0.z); pk0.w=tf32r(pk0.w);
            pk1.x=tf32r(pk1.x); pk1.y=tf32r(pk1.y); pk1.z=tf32r(pk1.z); pk1.w=tf32r(pk1.w);
            pv0.x=tf32r(pv0.x); pv0.y=tf32r(pv0.y); pv0.z=tf32r(pv0.z); pv0.w=tf32r(pv0.w);
            pv1.x=tf32r(pv1.x); pv1.y=tf32r(pv1.y); pv1.z=tf32r(pv1.z); pv1.w=tf32r(pv1.w);
            *(float4*)(Kd + sr0 * KSTR + sc0) = pk0;
            *(float4*)(Kd + sr1 * KSTR + sc1) = pk1;
            *(float4*)(Vd + sr0 * VSTR + sc0) = pv0;
            *(float4*)(Vd + sr1 * VSTR + sc1) = pv1;
        }
        __syncthreads();
    }

    // epilogue: divide by row sums, write [B, QL, H*DH] layout
    float inv[4];
#pragma unroll
    for (int r = 0; r < 4; r++) inv[r] = 1.0f / lrow[r];
#pragma unroll
    for (int nf = 0; nf < 8; nf++) {
        int col = nf * 8 + 2 * t;
        *(float2*)(Ob + (size_t)q0 * DINNER + col) =
            make_float2(oacc[nf][0] * inv[0], oacc[nf][1] * inv[0]);
        *(float2*)(Ob + (size_t)(q0 + 8) * DINNER + col) =
            make_float2(oacc[nf][2] * inv[1], oacc[nf][3] * inv[1]);
        *(float2*)(Ob + (size_t)(q0 + 16) * DINNER + col) =
            make_float2(oacc[nf][4] * inv[2], oacc[nf][5] * inv[2]);
        *(float2*)(Ob + (size_t)(q0 + 24) * DINNER + col) =
            make_float2(oacc[nf][6] * inv[3], oacc[nf][7] * inv[3]);
    }
}

// ---------------------------------------------------------------------------
// launch
// ---------------------------------------------------------------------------
extern "C" void kernel_launch(void* const* d_in, const int* in_sizes, int n_in,
                              void* d_out, int out_size)
{
    (void)in_sizes; (void)n_in; (void)out_size;
    const float* x   = (const float*)d_in[0];
    const float* ctx = (const float*)d_in[1];
    const float* Wq  = (const float*)d_in[2];
    const float* Wk  = (const float*)d_in[3];
    const float* Wv  = (const float*)d_in[4];
    const float* Wo  = (const float*)d_in[5];
    const float* bo  = (const float*)d_in[6];
    float* out = (float*)d_out;

    float *Qb, *Kb, *Vb, *Ab;
    cudaGetSymbolAddress((void**)&Qb, g_Q);
    cudaGetSymbolAddress((void**)&Kb, g_K);
    cudaGetSymbolAddress((void**)&Vb, g_V);
    cudaGetSymbolAddress((void**)&Ab, g_A);
    cudaFuncSetAttribute(flash_attn, cudaFuncAttributeMaxDynamicSharedMemorySize,
                         ATT_SMEM);

    dim3 blk(256);
    dim3 gProj(DINNER / GBN, MROWS / GBM);   // (4, 64)

    gemm_tf32<<<gProj, blk>>>(x,   Wq, Qb, nullptr, MROWS, DINNER, SQD);
    gemm_tf32<<<gProj, blk>>>(ctx, Wk, Kb, nullptr, MROWS, DINNER, SCD);
    gemm_tf32<<<gProj, blk>>>(ctx, Wv, Vb, nullptr, MROWS, DINNER, SCD);
    flash_attn<<<dim3(SQL / 256, NHEADS, NB), blk, ATT_SMEM>>>(Qb, Kb, Vb, Ab);
    gemm_tf32<<<dim3(SQD / GBN, MROWS / GBM), blk>>>(Ab, Wo, out, bo,
                                                     MROWS, SQD, DINNER);
}

// round 5
// speedup vs baseline: 1.2967x; 1.0007x over previous
#include <cuda_runtime.h>
#include <cstdint>
#include <cstddef>

// Problem constants
#define NB      2
#define SQL     4096
#define SKL     4096
#define SQD     512
#define SCD     768
#define NHEADS  8
#define HDIM    64
#define DINNER  512
#define MROWS   (NB*SQL)   // 8192

// Scratch (allocation-free rule: __device__ globals)
__device__ float g_Q[(size_t)MROWS * DINNER];
__device__ float g_K[(size_t)MROWS * DINNER];
__device__ float g_V[(size_t)MROWS * DINNER];
__device__ float g_A[(size_t)MROWS * DINNER];

// ---------------------------------------------------------------------------
// helpers
// ---------------------------------------------------------------------------
__device__ __forceinline__ unsigned f2tf(float x) {
    unsigned u;
    asm("cvt.rna.tf32.f32 %0, %1;" : "=r"(u) : "f"(x));
    return u;
}
__device__ __forceinline__ float tf32r(float x) { return __uint_as_float(f2tf(x)); }

__device__ __forceinline__ float ex2(float x) {
    float r;
    asm("ex2.approx.ftz.f32 %0, %1;" : "=f"(r) : "f"(x));
    return r;
}

// D = A(16x8, tf32, row) * B(8x8, tf32, col) + C, fp32 accum
__device__ __forceinline__ void mma8(float* c,
                                     unsigned a0, unsigned a1, unsigned a2, unsigned a3,
                                     unsigned b0, unsigned b1) {
    asm volatile(
        "mma.sync.aligned.m16n8k8.row.col.f32.tf32.tf32.f32 "
        "{%0,%1,%2,%3}, {%4,%5,%6,%7}, {%8,%9}, {%0,%1,%2,%3};\n"
        : "+f"(c[0]), "+f"(c[1]), "+f"(c[2]), "+f"(c[3])
        : "r"(a0), "r"(a1), "r"(a2), "r"(a3), "r"(b0), "r"(b1));
}

// ---------------------------------------------------------------------------
// Generic TF32 GEMM: C[M,N] = A[M,K] @ B[K,N] (+bias), all fp32 row-major.
// BM=128, BN=128, BK=16, 256 threads (8 warps as 2x4), warp tile 64x32.
// ---------------------------------------------------------------------------
#define GBM 128
#define GBN 128
#define GBK 16
#define ASTR 20
#define BSTR 136

__global__ __launch_bounds__(256, 2) void gemm_tf32(
    const float* __restrict__ A, const float* __restrict__ B,
    float* __restrict__ C, const float* __restrict__ bias,
    int M, int N, int K)
{
    __shared__ __align__(16) float As[GBM * ASTR];
    __shared__ __align__(16) float Bs[GBK * BSTR];

    const int tid  = threadIdx.x;
    const int warp = tid >> 5, lane = tid & 31;
    const int g = lane >> 2, t = lane & 3;
    const int wm = warp >> 2, wn = warp & 3;
    const int mBase = blockIdx.y * GBM;
    const int nBase = blockIdx.x * GBN;

    float acc[4][4][4];
#pragma unroll
    for (int i = 0; i < 4; i++)
#pragma unroll
        for (int j = 0; j < 4; j++)
#pragma unroll
            for (int c = 0; c < 4; c++) acc[i][j][c] = 0.f;

#pragma unroll 1
    for (int k0 = 0; k0 < K; k0 += GBK) {
#pragma unroll
        for (int i = 0; i < 2; i++) {
            int idx = tid + i * 256;
            int r = idx >> 2, c4 = (idx & 3) * 4;
            float4 v = *(const float4*)(A + (size_t)(mBase + r) * K + k0 + c4);
            v.x = tf32r(v.x); v.y = tf32r(v.y); v.z = tf32r(v.z); v.w = tf32r(v.w);
            *(float4*)(As + r * ASTR + c4) = v;
        }
#pragma unroll
        for (int i = 0; i < 2; i++) {
            int idx = tid + i * 256;
            int r = idx >> 5, c4 = (idx & 31) * 4;
            float4 v = *(const float4*)(B + (size_t)(k0 + r) * N + nBase + c4);
            v.x = tf32r(v.x); v.y = tf32r(v.y); v.z = tf32r(v.z); v.w = tf32r(v.w);
            *(float4*)(Bs + r * BSTR + c4) = v;
        }
        __syncthreads();

#pragma unroll
        for (int kk = 0; kk < 2; kk++) {
            unsigned af[4][4];
#pragma unroll
            for (int mf = 0; mf < 4; mf++) {
                int rb = (wm * 64 + mf * 16 + g) * ASTR + kk * 8 + t;
                af[mf][0] = __float_as_uint(As[rb]);
                af[mf][1] = __float_as_uint(As[rb + 8 * ASTR]);
                af[mf][2] = __float_as_uint(As[rb + 4]);
                af[mf][3] = __float_as_uint(As[rb + 8 * ASTR + 4]);
            }
            unsigned bf[4][2];
#pragma unroll
            for (int nf = 0; nf < 4; nf++) {
                int cb = wn * 32 + nf * 8 + g;
                bf[nf][0] = __float_as_uint(Bs[(kk * 8 + t) * BSTR + cb]);
                bf[nf][1] = __float_as_uint(Bs[(kk * 8 + t + 4) * BSTR + cb]);
            }
#pragma unroll
            for (int mf = 0; mf < 4; mf++)
#pragma unroll
                for (int nf = 0; nf < 4; nf++)
                    mma8(acc[mf][nf], af[mf][0], af[mf][1], af[mf][2], af[mf][3],
                         bf[nf][0], bf[nf][1]);
        }
        __syncthreads();
    }

#pragma unroll
    for (int mf = 0; mf < 4; mf++) {
        int r0 = mBase + wm * 64 + mf * 16 + g;
#pragma unroll
        for (int nf = 0; nf < 4; nf++) {
            int col = nBase + wn * 32 + nf * 8 + 2 * t;
            float b0 = 0.f, b1 = 0.f;
            if (bias) { b0 = bias[col]; b1 = bias[col + 1]; }
            *(float2*)(C + (size_t)r0 * N + col) =
                make_float2(acc[mf][nf][0] + b0, acc[mf][nf][1] + b1);
            *(float2*)(C + (size_t)(r0 + 8) * N + col) =
                make_float2(acc[mf][nf][2] + b0, acc[mf][nf][3] + b1);
        }
    }
}

// ---------------------------------------------------------------------------
// Flash attention v2: one CTA = (b, h, 256 q-rows), 8 warps, M=32 rows/warp
// (two m16 tiles at +0 and +16). KV processed in 32-key tiles, double-buffered
// smem with register prefetch. Softmax in log2 domain (ex2).
// ---------------------------------------------------------------------------
#define TKEY 32
#define NT   (SKL / TKEY)          // 128 tiles
#define KSTR 68                    // 64-col K tile rows, conflict-free B-frags
#define VSTR 72                    // 64-col V tile rows, conflict-free B-frags
#define PSTR 36                    // 32-col P tile rows, conflict-free A-frags
#define KBUF (TKEY * KSTR)         // 2176 floats
#define VBUF (TKEY * VSTR)         // 2304 floats
#define ATT_SMEM ((2 * (KBUF + VBUF) + 8 * 32 * PSTR) * 4)   // 72704 bytes

__global__ __launch_bounds__(256) void flash_attn(
    const float* __restrict__ Q, const float* __restrict__ Kg,
    const float* __restrict__ Vg, float* __restrict__ O)
{
    extern __shared__ __align__(16) float sm[];
    // layout: Ks0, Vs0, Ks1, Vs1, P
    float* Ps = sm + 2 * (KBUF + VBUF);

    const int tid  = threadIdx.x;
    const int warp = tid >> 5, lane = tid & 31;
    const int g = lane >> 2, t = lane & 3;
    const int h = blockIdx.y, b = blockIdx.z;
    // scale * log2(e): softmax done in base-2
    const float scale = 0.125f * 1.44269504088896340736f;

    const float* Qb = Q  + (size_t)b * SQL * DINNER + h * HDIM;
    const float* Kb = Kg + (size_t)b * SKL * DINNER + h * HDIM;
    const float* Vb = Vg + (size_t)b * SKL * DINNER + h * HDIM;
    float*       Ob = O  + (size_t)b * SQL * DINNER + h * HDIM;
    float*       Pw = Ps + warp * 32 * PSTR;

    const int q0 = blockIdx.x * 256 + warp * 32 + g;  // rows q0,+8,+16,+24

    // Q fragments for M=32 (two m16 tiles), scale folded, tf32-rounded.
    unsigned qf[8][8];
#pragma unroll
    for (int kk = 0; kk < 8; kk++) {
        int c = kk * 8 + t;
#pragma unroll
        for (int half = 0; half < 2; half++) {
            int r = q0 + half * 16;
            qf[kk][half * 4 + 0] = f2tf(Qb[(size_t)r * DINNER + c] * scale);
            qf[kk][half * 4 + 1] = f2tf(Qb[(size_t)(r + 8) * DINNER + c] * scale);
            qf[kk][half * 4 + 2] = f2tf(Qb[(size_t)r * DINNER + c + 4] * scale);
            qf[kk][half * 4 + 3] = f2tf(Qb[(size_t)(r + 8) * DINNER + c + 4] * scale);
        }
    }

    float oacc[8][8];
#pragma unroll
    for (int nf = 0; nf < 8; nf++)
#pragma unroll
        for (int c = 0; c < 8; c++) oacc[nf][c] = 0.f;

    float mrow[4], lrow[4];
#pragma unroll
    for (int r = 0; r < 4; r++) { mrow[r] = -1e30f; lrow[r] = 0.f; }

    // staging indices: 512 float4 per 32x64 tile, 2 per thread
    const int sr0 = tid >> 4,          sc0 = (tid & 15) * 4;
    const int sr1 = (tid + 256) >> 4,  sc1 = (tid & 15) * 4;

    // preload tile 0
    {
        float4 k0 = *(const float4*)(Kb + (size_t)sr0 * DINNER + sc0);
        float4 k1 = *(const float4*)(Kb + (size_t)sr1 * DINNER + sc1);
        float4 v0 = *(const float4*)(Vb + (size_t)sr0 * DINNER + sc0);
        float4 v1 = *(const float4*)(Vb + (size_t)sr1 * DINNER + sc1);
        k0.x=tf32r(k0.x); k0.y=tf32r(k0.y); k0.z=tf32r(k0.z); k0.w=tf32r(k0.w);
        k1.x=tf32r(k1.x); k1.y=tf32r(k1.y); k1.z=tf32r(k1.z); k1.w=tf32r(k1.w);
        v0.x=tf32r(v0.x); v0.y=tf32r(v0.y); v0.z=tf32r(v0.z); v0.w=tf32r(v0.w);
        v1.x=tf32r(v1.x); v1.y=tf32r(v1.y); v1.z=tf32r(v1.z); v1.w=tf32r(v1.w);
        *(float4*)(sm + sr0 * KSTR + sc0) = k0;
        *(float4*)(sm + sr1 * KSTR + sc1) = k1;
        *(float4*)(sm + KBUF + sr0 * VSTR + sc0) = v0;
        *(float4*)(sm + KBUF + sr1 * VSTR + sc1) = v1;
    }
    __syncthreads();

#pragma unroll 1
    for (int it = 0; it < NT; it++) {
        // prefetch next tile into registers
        float4 pk0, pk1, pv0, pv1;
        const bool more = (it + 1 < NT);
        if (more) {
            const float* Kn = Kb + (size_t)(it + 1) * TKEY * DINNER;
            const float* Vn = Vb + (size_t)(it + 1) * TKEY * DINNER;
            pk0 = *(const float4*)(Kn + (size_t)sr0 * DINNER + sc0);
            pk1 = *(const float4*)(Kn + (size_t)sr1 * DINNER + sc1);
            pv0 = *(const float4*)(Vn + (size_t)sr0 * DINNER + sc0);
            pv1 = *(const float4*)(Vn + (size_t)sr1 * DINNER + sc1);
        }

        float* Ks = sm + (it & 1) * (KBUF + VBUF);
        float* Vs = Ks + KBUF;

        // S = Q @ K^T : M=32 (2 m16), N=32 keys (4 n8 groups), K=64 dh
        float s[4][8];
#pragma unroll
        for (int nf = 0; nf < 4; nf++)
#pragma unroll
            for (int c = 0; c < 8; c++) s[nf][c] = 0.f;
#pragma unroll
        for (int kk = 0; kk < 8; kk++) {
#pragma unroll
            for (int nf = 0; nf < 4; nf++) {
                unsigned b0 = __float_as_uint(Ks[(nf * 8 + g) * KSTR + kk * 8 + t]);
                unsigned b1 = __float_as_uint(Ks[(nf * 8 + g) * KSTR + kk * 8 + t + 4]);
                mma8(&s[nf][0], qf[kk][0], qf[kk][1], qf[kk][2], qf[kk][3], b0, b1);
                mma8(&s[nf][4], qf[kk][4], qf[kk][5], qf[kk][6], qf[kk][7], b0, b1);
            }
        }

        // online softmax over 4 row-groups (rows q0, q0+8, q0+16, q0+24)
        float tm[4];
#pragma unroll
        for (int r = 0; r < 4; r++) tm[r] = -1e30f;
#pragma unroll
        for (int nf = 0; nf < 4; nf++) {
            tm[0] = fmaxf(tm[0], fmaxf(s[nf][0], s[nf][1]));
            tm[1] = fmaxf(tm[1], fmaxf(s[nf][2], s[nf][3]));
            tm[2] = fmaxf(tm[2], fmaxf(s[nf][4], s[nf][5]));
            tm[3] = fmaxf(tm[3], fmaxf(s[nf][6], s[nf][7]));
        }
#pragma unroll
        for (int r = 0; r < 4; r++) {
            tm[r] = fmaxf(tm[r], __shfl_xor_sync(0xffffffffu, tm[r], 1));
            tm[r] = fmaxf(tm[r], __shfl_xor_sync(0xffffffffu, tm[r], 2));
        }
        float nm[4], al[4], rs[4];
#pragma unroll
        for (int r = 0; r < 4; r++) {
            nm[r] = fmaxf(mrow[r], tm[r]);
            al[r] = ex2(mrow[r] - nm[r]);
            rs[r] = 0.f;
        }
#pragma unroll
        for (int nf = 0; nf < 4; nf++) {
            float p0 = ex2(s[nf][0] - nm[0]);
            float p1 = ex2(s[nf][1] - nm[0]);
            float p2 = ex2(s[nf][2] - nm[1]);
            float p3 = ex2(s[nf][3] - nm[1]);
            float p4 = ex2(s[nf][4] - nm[2]);
            float p5 = ex2(s[nf][5] - nm[2]);
            float p6 = ex2(s[nf][6] - nm[3]);
            float p7 = ex2(s[nf][7] - nm[3]);
            rs[0] += p0 + p1; rs[1] += p2 + p3;
            rs[2] += p4 + p5; rs[3] += p6 + p7;
            int cb = nf * 8 + 2 * t;
            *(float2*)(Pw + g * PSTR + cb)        = make_float2(tf32r(p0), tf32r(p1));
            *(float2*)(Pw + (g + 8) * PSTR + cb)  = make_float2(tf32r(p2), tf32r(p3));
            *(float2*)(Pw + (g + 16) * PSTR + cb) = make_float2(tf32r(p4), tf32r(p5));
            *(float2*)(Pw + (g + 24) * PSTR + cb) = make_float2(tf32r(p6), tf32r(p7));
        }
#pragma unroll
        for (int r = 0; r < 4; r++) {
            rs[r] += __shfl_xor_sync(0xffffffffu, rs[r], 1);
            rs[r] += __shfl_xor_sync(0xffffffffu, rs[r], 2);
            lrow[r] = lrow[r] * al[r] + rs[r];
            mrow[r] = nm[r];
        }
#pragma unroll
        for (int nf = 0; nf < 8; nf++) {
            oacc[nf][0] *= al[0]; oacc[nf][1] *= al[0];
            oacc[nf][2] *= al[1]; oacc[nf][3] *= al[1];
            oacc[nf][4] *= al[2]; oacc[nf][5] *= al[2];
            oacc[nf][6] *= al[3]; oacc[nf][7] *= al[3];
        }
        __syncwarp();   // P tile visible within warp

        // O += P @ V : M=32, N=64 dh, K=32 keys (4 k8 groups)
#pragma unroll
        for (int kk = 0; kk < 4; kk++) {
            unsigned a0 = __float_as_uint(Pw[g * PSTR + kk * 8 + t]);
            unsigned a1 = __float_as_uint(Pw[(g + 8) * PSTR + kk * 8 + t]);
            unsigned a2 = __float_as_uint(Pw[g * PSTR + kk * 8 + t + 4]);
            unsigned a3 = __float_as_uint(Pw[(g + 8) * PSTR + kk * 8 + t + 4]);
            unsigned a4 = __float_as_uint(Pw[(g + 16) * PSTR + kk * 8 + t]);
            unsigned a5 = __float_as_uint(Pw[(g + 24) * PSTR + kk * 8 + t]);
            unsigned a6 = __float_as_uint(Pw[(g + 16) * PSTR + kk * 8 + t + 4]);
            unsigned a7 = __float_as_uint(Pw[(g + 24) * PSTR + kk * 8 + t + 4]);
#pragma unroll
            for (int nf = 0; nf < 8; nf++) {
                unsigned b0 = __float_as_uint(Vs[(kk * 8 + t) * VSTR + nf * 8 + g]);
                unsigned b1 = __float_as_uint(Vs[(kk * 8 + t + 4) * VSTR + nf * 8 + g]);
                mma8(&oacc[nf][0], a0, a1, a2, a3, b0, b1);
                mma8(&oacc[nf][4], a4, a5, a6, a7, b0, b1);
            }
        }

        // stage prefetched tile into the other buffer
        if (more) {
            float* Kd = sm + ((it + 1) & 1) * (KBUF + VBUF);
            float* Vd = Kd + KBUF;
            pk0.x=tf32r(pk0.x); pk0.y=tf32r(pk0.y); pk0.z=tf32r(pk0.z); pk0.w=tf32r(pk0.w);
            pk1.x=tf32r(pk1.x); pk1.y=tf32r(pk1.y); pk1.z=tf32r(pk1.z); pk1.w=tf32r(pk1.w);
            pv0.x=tf32r(pv0.x); pv0.y=tf32r(pv0.y); pv0.z=tf32r(pv0.z); pv0.w=tf32r(pv0.w);
            pv1.x=tf32r(pv1.x); pv1.y=tf32r(pv1.y); pv1.z=tf32r(pv1.z); pv1.w=tf32r(pv1.w);
            *(float4*)(Kd + sr0 * KSTR + sc0) = pk0;
            *(float4*)(Kd + sr1 * KSTR + sc1) = pk1;
            *(float4*)(Vd + sr0 * VSTR + sc0) = pv0;
            *(float4*)(Vd + sr1 * VSTR + sc1) = pv1;
        }
        __syncthreads();
    }

    // epilogue: divide by row sums, write [B, QL, H*DH] layout
    float inv[4];
#pragma unroll
    for (int r = 0; r < 4; r++) inv[r] = 1.0f / lrow[r];
#pragma unroll
    for (int nf = 0; nf < 8; nf++) {
        int col = nf * 8 + 2 * t;
        *(float2*)(Ob + (size_t)q0 * DINNER + col) =
            make_float2(oacc[nf][0] * inv[0], oacc[nf][1] * inv[0]);
        *(float2*)(Ob + (size_t)(q0 + 8) * DINNER + col) =
            make_float2(oacc[nf][2] * inv[1], oacc[nf][3] * inv[1]);
        *(float2*)(Ob + (size_t)(q0 + 16) * DINNER + col) =
            make_float2(oacc[nf][4] * inv[2], oacc[nf][5] * inv[2]);
        *(float2*)(Ob + (size_t)(q0 + 24) * DINNER + col) =
            make_float2(oacc[nf][6] * inv[3], oacc[nf][7] * inv[3]);
    }
}

// ---------------------------------------------------------------------------
// launch
// ---------------------------------------------------------------------------
extern "C" void kernel_launch(void* const* d_in, const int* in_sizes, int n_in,
                              void* d_out, int out_size)
{
    (void)in_sizes; (void)n_in; (void)out_size;
    const float* x   = (const float*)d_in[0];
    const float* ctx = (const float*)d_in[1];
    const float* Wq  = (const float*)d_in[2];
    const float* Wk  = (const float*)d_in[3];
    const float* Wv  = (const float*)d_in[4];
    const float* Wo  = (const float*)d_in[5];
    const float* bo  = (const float*)d_in[6];
    float* out = (float*)d_out;

    float *Qb, *Kb, *Vb, *Ab;
    cudaGetSymbolAddress((void**)&Qb, g_Q);
    cudaGetSymbolAddress((void**)&Kb, g_K);
    cudaGetSymbolAddress((void**)&Vb, g_V);
    cudaGetSymbolAddress((void**)&Ab, g_A);
    cudaFuncSetAttribute(flash_attn, cudaFuncAttributeMaxDynamicSharedMemorySize,
                         ATT_SMEM);

    dim3 blk(256);
    dim3 gProj(DINNER / GBN, MROWS / GBM);   // (4, 64)

    gemm_tf32<<<gProj, blk>>>(x,   Wq, Qb, nullptr, MROWS, DINNER, SQD);
    gemm_tf32<<<gProj, blk>>>(ctx, Wk, Kb, nullptr, MROWS, DINNER, SCD);
    gemm_tf32<<<gProj, blk>>>(ctx, Wv, Vb, nullptr, MROWS, DINNER, SCD);
    flash_attn<<<dim3(SQL / 256, NHEADS, NB), blk, ATT_SMEM>>>(Qb, Kb, Vb, Ab);
    gemm_tf32<<<dim3(SQD / GBN, MROWS / GBM), blk>>>(Ab, Wo, out, bo,
                                                     MROWS, SQD, DINNER);
}

// round 7
// speedup vs baseline: 1.3571x; 1.0466x over previous
#include <cuda_runtime.h>
#include <cuda_fp16.h>
#include <cstdint>
#include <cstddef>

// Problem constants
#define NB      2
#define SQL     4096
#define SKL     4096
#define SQD     512
#define SCD     768
#define NHEADS  8
#define HDIM    64
#define DINNER  512
#define MROWS   (NB*SQL)   // 8192

// Scratch (allocation-free rule: __device__ globals)
__device__ float g_Q[(size_t)MROWS * DINNER];
__device__ float g_K[(size_t)MROWS * DINNER];
__device__ float g_V[(size_t)MROWS * DINNER];
__device__ float g_A[(size_t)MROWS * DINNER];

// ---------------------------------------------------------------------------
// helpers
// ---------------------------------------------------------------------------
__device__ __forceinline__ unsigned f2tf(float x) {
    unsigned u;
    asm("cvt.rna.tf32.f32 %0, %1;" : "=r"(u) : "f"(x));
    return u;
}
__device__ __forceinline__ float tf32r(float x) { return __uint_as_float(f2tf(x)); }

__device__ __forceinline__ float ex2(float x) {
    float r;
    asm("ex2.approx.ftz.f32 %0, %1;" : "=f"(r) : "f"(x));
    return r;
}

__device__ __forceinline__ unsigned packh2(float a, float b) {
    __half2 h = __floats2half2_rn(a, b);
    return *reinterpret_cast<unsigned*>(&h);
}

// D = A(16x8, tf32, row) * B(8x8, tf32, col) + C, fp32 accum
__device__ __forceinline__ void mma8(float* c,
                                     unsigned a0, unsigned a1, unsigned a2, unsigned a3,
                                     unsigned b0, unsigned b1) {
    asm volatile(
        "mma.sync.aligned.m16n8k8.row.col.f32.tf32.tf32.f32 "
        "{%0,%1,%2,%3}, {%4,%5,%6,%7}, {%8,%9}, {%0,%1,%2,%3};\n"
        : "+f"(c[0]), "+f"(c[1]), "+f"(c[2]), "+f"(c[3])
        : "r"(a0), "r"(a1), "r"(a2), "r"(a3), "r"(b0), "r"(b1));
}

// D = A(16x16, f16, row) * B(16x8, f16, col) + C, fp32 accum
__device__ __forceinline__ void mma16h(float* c,
                                       unsigned a0, unsigned a1, unsigned a2, unsigned a3,
                                       unsigned b0, unsigned b1) {
    asm volatile(
        "mma.sync.aligned.m16n8k16.row.col.f32.f16.f16.f32 "
        "{%0,%1,%2,%3}, {%4,%5,%6,%7}, {%8,%9}, {%0,%1,%2,%3};\n"
        : "+f"(c[0]), "+f"(c[1]), "+f"(c[2]), "+f"(c[3])
        : "r"(a0), "r"(a1), "r"(a2), "r"(a3), "r"(b0), "r"(b1));
}

__device__ __forceinline__ void ldsm4(unsigned* r, uint32_t addr) {
    asm volatile(
        "ldmatrix.sync.aligned.m8n8.x4.shared.b16 {%0,%1,%2,%3}, [%4];"
        : "=r"(r[0]), "=r"(r[1]), "=r"(r[2]), "=r"(r[3]) : "r"(addr));
}
__device__ __forceinline__ void ldsm4t(unsigned* r, uint32_t addr) {
    asm volatile(
        "ldmatrix.sync.aligned.m8n8.x4.trans.shared.b16 {%0,%1,%2,%3}, [%4];"
        : "=r"(r[0]), "=r"(r[1]), "=r"(r[2]), "=r"(r[3]) : "r"(addr));
}
__device__ __forceinline__ void stsm4(uint32_t addr, unsigned r0, unsigned r1,
                                      unsigned r2, unsigned r3) {
    asm volatile(
        "stmatrix.sync.aligned.m8n8.x4.shared.b16 [%0], {%1,%2,%3,%4};"
        :: "r"(addr), "r"(r0), "r"(r1), "r"(r2), "r"(r3));
}

// ---------------------------------------------------------------------------
// Generic TF32 GEMM (unchanged): C[M,N] = A[M,K] @ B[K,N] (+bias)
// ---------------------------------------------------------------------------
#define GBM 128
#define GBN 128
#define GBK 16
#define ASTR 20
#define BSTR 136

__global__ __launch_bounds__(256, 2) void gemm_tf32(
    const float* __restrict__ A, const float* __restrict__ B,
    float* __restrict__ C, const float* __restrict__ bias,
    int M, int N, int K)
{
    __shared__ __align__(16) float As[GBM * ASTR];
    __shared__ __align__(16) float Bs[GBK * BSTR];

    const int tid  = threadIdx.x;
    const int warp = tid >> 5, lane = tid & 31;
    const int g = lane >> 2, t = lane & 3;
    const int wm = warp >> 2, wn = warp & 3;
    const int mBase = blockIdx.y * GBM;
    const int nBase = blockIdx.x * GBN;

    float acc[4][4][4];
#pragma unroll
    for (int i = 0; i < 4; i++)
#pragma unroll
        for (int j = 0; j < 4; j++)
#pragma unroll
            for (int c = 0; c < 4; c++) acc[i][j][c] = 0.f;

#pragma unroll 1
    for (int k0 = 0; k0 < K; k0 += GBK) {
#pragma unroll
        for (int i = 0; i < 2; i++) {
            int idx = tid + i * 256;
            int r = idx >> 2, c4 = (idx & 3) * 4;
            float4 v = *(const float4*)(A + (size_t)(mBase + r) * K + k0 + c4);
            v.x = tf32r(v.x); v.y = tf32r(v.y); v.z = tf32r(v.z); v.w = tf32r(v.w);
            *(float4*)(As + r * ASTR + c4) = v;
        }
#pragma unroll
        for (int i = 0; i < 2; i++) {
            int idx = tid + i * 256;
            int r = idx >> 5, c4 = (idx & 31) * 4;
            float4 v = *(const float4*)(B + (size_t)(k0 + r) * N + nBase + c4);
            v.x = tf32r(v.x); v.y = tf32r(v.y); v.z = tf32r(v.z); v.w = tf32r(v.w);
            *(float4*)(Bs + r * BSTR + c4) = v;
        }
        __syncthreads();

#pragma unroll
        for (int kk = 0; kk < 2; kk++) {
            unsigned af[4][4];
#pragma unroll
            for (int mf = 0; mf < 4; mf++) {
                int rb = (wm * 64 + mf * 16 + g) * ASTR + kk * 8 + t;
                af[mf][0] = __float_as_uint(As[rb]);
                af[mf][1] = __float_as_uint(As[rb + 8 * ASTR]);
                af[mf][2] = __float_as_uint(As[rb + 4]);
                af[mf][3] = __float_as_uint(As[rb + 8 * ASTR + 4]);
            }
            unsigned bf[4][2];
#pragma unroll
            for (int nf = 0; nf < 4; nf++) {
                int cb = wn * 32 + nf * 8 + g;
                bf[nf][0] = __float_as_uint(Bs[(kk * 8 + t) * BSTR + cb]);
                bf[nf][1] = __float_as_uint(Bs[(kk * 8 + t + 4) * BSTR + cb]);
            }
#pragma unroll
            for (int mf = 0; mf < 4; mf++)
#pragma unroll
                for (int nf = 0; nf < 4; nf++)
                    mma8(acc[mf][nf], af[mf][0], af[mf][1], af[mf][2], af[mf][3],
                         bf[nf][0], bf[nf][1]);
        }
        __syncthreads();
    }

#pragma unroll
    for (int mf = 0; mf < 4; mf++) {
        int r0 = mBase + wm * 64 + mf * 16 + g;
#pragma unroll
        for (int nf = 0; nf < 4; nf++) {
            int col = nBase + wn * 32 + nf * 8 + 2 * t;
            float b0 = 0.f, b1 = 0.f;
            if (bias) { b0 = bias[col]; b1 = bias[col + 1]; }
            *(float2*)(C + (size_t)r0 * N + col) =
                make_float2(acc[mf][nf][0] + b0, acc[mf][nf][1] + b1);
            *(float2*)(C + (size_t)(r0 + 8) * N + col) =
                make_float2(acc[mf][nf][2] + b0, acc[mf][nf][3] + b1);
        }
    }
}

// ---------------------------------------------------------------------------
// Flash attention v3: tf32 QK^T (pair-packed K smem), fp16 P·V via
// stmatrix/ldmatrix, double-buffered KV, softmax in log2 domain.
// One CTA = (b, h, 256 q-rows), 8 warps, M=32 rows/warp, 32-key tiles.
// ---------------------------------------------------------------------------
#define TKEY   32
#define NT     (SKL / TKEY)           // 128 tiles
#define KSTRW  72                     // K tile row stride (4B words); 72%32==8
#define VSTRH  72                     // V tile row stride (halves); 36 words/row
#define PSTRH  40                     // P tile row stride (halves); 20 words/row
#define KBYTES (TKEY * KSTRW * 4)     // 9216
#define VBYTES (TKEY * VSTRH * 2)     // 4608
#define BUFBYTES (KBYTES + VBYTES)    // 13824
#define POFF   (2 * BUFBYTES)         // 27648
#define ATT_SMEM (POFF + 8 * 32 * PSTRH * 2)   // 48128 bytes

__global__ __launch_bounds__(256) void flash_attn(
    const float* __restrict__ Q, const float* __restrict__ Kg,
    const float* __restrict__ Vg, float* __restrict__ O)
{
    extern __shared__ __align__(128) char smc[];
    float* smf = (float*)smc;
    const uint32_t smem_u32 = (uint32_t)__cvta_generic_to_shared(smc);

    const int tid  = threadIdx.x;
    const int warp = tid >> 5, lane = tid & 31;
    const int g = lane >> 2, t = lane & 3;
    const int h = blockIdx.y, b = blockIdx.z;
    const float scale = 0.125f * 1.44269504088896340736f;   // dh^-1/2 * log2(e)

    const float* Qb = Q  + (size_t)b * SQL * DINNER + h * HDIM;
    const float* Kb = Kg + (size_t)b * SKL * DINNER + h * HDIM;
    const float* Vb = Vg + (size_t)b * SKL * DINNER + h * HDIM;
    float*       Ob = O  + (size_t)b * SQL * DINNER + h * HDIM;

    const int q0 = blockIdx.x * 256 + warp * 32 + g;   // rows q0,+8,+16,+24

    // ldmatrix/stmatrix lane geometry (shared by P and V tiles)
    const int lm_r  = (lane & 7) | (((lane >> 3) & 1) << 3);   // 0..15
    const int lm_c8 = (lane >> 4) << 3;                        // 0 or 8 halves

    const uint32_t Pbase = smem_u32 + POFF + warp * (32 * PSTRH * 2);
    const uint32_t pA    = Pbase + (lm_r * PSTRH + lm_c8) * 2; // + hh*16*PSTRH*2 + kk*32
    const uint32_t vLane = (lm_r * VSTRH + lm_c8) * 2;         // + buf + kk*16*VSTRH*2 + np*32

    // staging indices: one key-row chunk of 8 floats per thread
    const int sr  = tid & 31;      // key row 0..31
    const int sch = tid >> 5;      // chunk 0..7 (cols sch*8 .. +7)

    // Q fragments for M=32 (two m16 tiles), scale folded, tf32-rounded.
    unsigned qf[8][8];
#pragma unroll
    for (int kk = 0; kk < 8; kk++) {
        int c = kk * 8 + t;
#pragma unroll
        for (int half = 0; half < 2; half++) {
            int r = q0 + half * 16;
            qf[kk][half * 4 + 0] = f2tf(Qb[(size_t)r * DINNER + c] * scale);
            qf[kk][half * 4 + 1] = f2tf(Qb[(size_t)(r + 8) * DINNER + c] * scale);
            qf[kk][half * 4 + 2] = f2tf(Qb[(size_t)r * DINNER + c + 4] * scale);
            qf[kk][half * 4 + 3] = f2tf(Qb[(size_t)(r + 8) * DINNER + c + 4] * scale);
        }
    }

    float oacc[8][8];
#pragma unroll
    for (int nf = 0; nf < 8; nf++)
#pragma unroll
        for (int c = 0; c < 8; c++) oacc[nf][c] = 0.f;

    float mrow[4], lrow[4];
#pragma unroll
    for (int r = 0; r < 4; r++) { mrow[r] = -1e30f; lrow[r] = 0.f; }

    // ---- preload tile 0 ----
    {
        const float* Kr = Kb + (size_t)sr * DINNER + sch * 8;
        const float* Vr = Vb + (size_t)sr * DINNER + sch * 8;
        float4 ka = *(const float4*)Kr, kb4 = *(const float4*)(Kr + 4);
        float4 va = *(const float4*)Vr, vb4 = *(const float4*)(Vr + 4);
        float* kd = smf + (size_t)sr * KSTRW + sch * 8;
        *(float4*)kd       = make_float4(tf32r(ka.x), tf32r(kb4.x), tf32r(ka.y), tf32r(kb4.y));
        *(float4*)(kd + 4) = make_float4(tf32r(ka.z), tf32r(kb4.z), tf32r(ka.w), tf32r(kb4.w));
        uint4 vv;
        vv.x = packh2(va.x, va.y);  vv.y = packh2(va.z, va.w);
        vv.z = packh2(vb4.x, vb4.y); vv.w = packh2(vb4.z, vb4.w);
        *(uint4*)(smc + KBYTES + sr * (VSTRH * 2) + sch * 16) = vv;
    }
    __syncthreads();

#pragma unroll 1
    for (int it = 0; it < NT; it++) {
        // prefetch next tile into registers
        float4 pk0, pk1, pv0, pv1;
        const bool more = (it + 1 < NT);
        if (more) {
            const float* Kn = Kb + (size_t)(it + 1) * TKEY * DINNER + (size_t)sr * DINNER + sch * 8;
            const float* Vn = Vb + (size_t)(it + 1) * TKEY * DINNER + (size_t)sr * DINNER + sch * 8;
            pk0 = *(const float4*)Kn; pk1 = *(const float4*)(Kn + 4);
            pv0 = *(const float4*)Vn; pv1 = *(const float4*)(Vn + 4);
        }

        const int bufW = (it & 1) * (BUFBYTES / 4);
        const float* Ks = smf + bufW;
        const uint32_t vBufA = smem_u32 + (it & 1) * BUFBYTES + KBYTES + vLane;

        // ---- S = Q @ K^T : M=32, N=32 keys, K=64 dh (tf32) ----
        float s[4][8];
#pragma unroll
        for (int nf = 0; nf < 4; nf++)
#pragma unroll
            for (int c = 0; c < 8; c++) s[nf][c] = 0.f;
#pragma unroll
        for (int kk = 0; kk < 8; kk++) {
#pragma unroll
            for (int nf = 0; nf < 4; nf++) {
                float2 kv = *(const float2*)(Ks + (nf * 8 + g) * KSTRW + kk * 8 + 2 * t);
                unsigned b0 = __float_as_uint(kv.x);
                unsigned b1 = __float_as_uint(kv.y);
                mma8(&s[nf][0], qf[kk][0], qf[kk][1], qf[kk][2], qf[kk][3], b0, b1);
                mma8(&s[nf][4], qf[kk][4], qf[kk][5], qf[kk][6], qf[kk][7], b0, b1);
            }
        }

        // ---- online softmax over 4 row-groups ----
        float tm[4];
#pragma unroll
        for (int r = 0; r < 4; r++) tm[r] = -1e30f;
#pragma unroll
        for (int nf = 0; nf < 4; nf++) {
            tm[0] = fmaxf(tm[0], fmaxf(s[nf][0], s[nf][1]));
            tm[1] = fmaxf(tm[1], fmaxf(s[nf][2], s[nf][3]));
            tm[2] = fmaxf(tm[2], fmaxf(s[nf][4], s[nf][5]));
            tm[3] = fmaxf(tm[3], fmaxf(s[nf][6], s[nf][7]));
        }
#pragma unroll
        for (int r = 0; r < 4; r++) {
            tm[r] = fmaxf(tm[r], __shfl_xor_sync(0xffffffffu, tm[r], 1));
            tm[r] = fmaxf(tm[r], __shfl_xor_sync(0xffffffffu, tm[r], 2));
        }
        float nm[4], al[4], rs[4];
#pragma unroll
        for (int r = 0; r < 4; r++) {
            nm[r] = fmaxf(mrow[r], tm[r]);
            al[r] = ex2(mrow[r] - nm[r]);
            rs[r] = 0.f;
        }
#pragma unroll
        for (int nf = 0; nf < 4; nf++) {
            s[nf][0] = ex2(s[nf][0] - nm[0]);
            s[nf][1] = ex2(s[nf][1] - nm[0]);
            s[nf][2] = ex2(s[nf][2] - nm[1]);
            s[nf][3] = ex2(s[nf][3] - nm[1]);
            s[nf][4] = ex2(s[nf][4] - nm[2]);
            s[nf][5] = ex2(s[nf][5] - nm[2]);
            s[nf][6] = ex2(s[nf][6] - nm[3]);
            s[nf][7] = ex2(s[nf][7] - nm[3]);
            rs[0] += s[nf][0] + s[nf][1]; rs[1] += s[nf][2] + s[nf][3];
            rs[2] += s[nf][4] + s[nf][5]; rs[3] += s[nf][6] + s[nf][7];
        }
#pragma unroll
        for (int r = 0; r < 4; r++) {
            rs[r] += __shfl_xor_sync(0xffffffffu, rs[r], 1);
            rs[r] += __shfl_xor_sync(0xffffffffu, rs[r], 2);
            lrow[r] = lrow[r] * al[r] + rs[r];
            mrow[r] = nm[r];
        }
#pragma unroll
        for (int nf = 0; nf < 8; nf++) {
            oacc[nf][0] *= al[0]; oacc[nf][1] *= al[0];
            oacc[nf][2] *= al[1]; oacc[nf][3] *= al[1];
            oacc[nf][4] *= al[2]; oacc[nf][5] *= al[2];
            oacc[nf][6] *= al[3]; oacc[nf][7] *= al[3];
        }

        // ---- P (half) -> smem via stmatrix ----
#pragma unroll
        for (int hh = 0; hh < 2; hh++)
#pragma unroll
            for (int kk = 0; kk < 2; kk++) {
                unsigned r0 = packh2(s[2*kk][hh*4 + 0],   s[2*kk][hh*4 + 1]);
                unsigned r1 = packh2(s[2*kk][hh*4 + 2],   s[2*kk][hh*4 + 3]);
                unsigned r2 = packh2(s[2*kk+1][hh*4 + 0], s[2*kk+1][hh*4 + 1]);
                unsigned r3 = packh2(s[2*kk+1][hh*4 + 2], s[2*kk+1][hh*4 + 3]);
                stsm4(pA + hh * (16 * PSTRH * 2) + kk * 32, r0, r1, r2, r3);
            }
        __syncwarp();

        // ---- O += P @ V : fp16 m16n8k16, B via ldmatrix.trans ----
#pragma unroll
        for (int kk = 0; kk < 2; kk++) {
            unsigned vb[4][4];
#pragma unroll
            for (int np = 0; np < 4; np++)
                ldsm4t(vb[np], vBufA + kk * (16 * VSTRH * 2) + np * 32);
            unsigned pa0[4], pa1[4];
            ldsm4(pa0, pA + kk * 32);
            ldsm4(pa1, pA + 16 * PSTRH * 2 + kk * 32);
#pragma unroll
            for (int nf = 0; nf < 8; nf++) {
                unsigned b0 = vb[nf >> 1][(nf & 1) * 2];
                unsigned b1 = vb[nf >> 1][(nf & 1) * 2 + 1];
                mma16h(&oacc[nf][0], pa0[0], pa0[1], pa0[2], pa0[3], b0, b1);
                mma16h(&oacc[nf][4], pa1[0], pa1[1], pa1[2], pa1[3], b0, b1);
            }
        }

        // ---- stage prefetched tile into the other buffer ----
        if (more) {
            const int nb = ((it + 1) & 1);
            float* kd = smf + nb * (BUFBYTES / 4) + (size_t)sr * KSTRW + sch * 8;
            *(float4*)kd       = make_float4(tf32r(pk0.x), tf32r(pk1.x), tf32r(pk0.y), tf32r(pk1.y));
            *(float4*)(kd + 4) = make_float4(tf32r(pk0.z), tf32r(pk1.z), tf32r(pk0.w), tf32r(pk1.w));
            uint4 vv;
            vv.x = packh2(pv0.x, pv0.y); vv.y = packh2(pv0.z, pv0.w);
            vv.z = packh2(pv1.x, pv1.y); vv.w = packh2(pv1.z, pv1.w);
            *(uint4*)(smc + nb * BUFBYTES + KBYTES + sr * (VSTRH * 2) + sch * 16) = vv;
        }
        __syncthreads();
    }

    // ---- epilogue: divide by row sums, write [B, QL, H*DH] layout ----
    float inv[4];
#pragma unroll
    for (int r = 0; r < 4; r++) inv[r] = 1.0f / lrow[r];
#pragma unroll
    for (int nf = 0; nf < 8; nf++) {
        int col = nf * 8 + 2 * t;
        *(float2*)(Ob + (size_t)q0 * DINNER + col) =
            make_float2(oacc[nf][0] * inv[0], oacc[nf][1] * inv[0]);
        *(float2*)(Ob + (size_t)(q0 + 8) * DINNER + col) =
            make_float2(oacc[nf][2] * inv[1], oacc[nf][3] * inv[1]);
        *(float2*)(Ob + (size_t)(q0 + 16) * DINNER + col) =
            make_float2(oacc[nf][4] * inv[2], oacc[nf][5] * inv[2]);
        *(float2*)(Ob + (size_t)(q0 + 24) * DINNER + col) =
            make_float2(oacc[nf][6] * inv[3], oacc[nf][7] * inv[3]);
    }
}

// ---------------------------------------------------------------------------
// launch
// ---------------------------------------------------------------------------
extern "C" void kernel_launch(void* const* d_in, const int* in_sizes, int n_in,
                              void* d_out, int out_size)
{
    (void)in_sizes; (void)n_in; (void)out_size;
    const float* x   = (const float*)d_in[0];
    const float* ctx = (const float*)d_in[1];
    const float* Wq  = (const float*)d_in[2];
    const float* Wk  = (const float*)d_in[3];
    const float* Wv  = (const float*)d_in[4];
    const float* Wo  = (const float*)d_in[5];
    const float* bo  = (const float*)d_in[6];
    float* out = (float*)d_out;

    float *Qb, *Kb, *Vb, *Ab;
    cudaGetSymbolAddress((void**)&Qb, g_Q);
    cudaGetSymbolAddress((void**)&Kb, g_K);
    cudaGetSymbolAddress((void**)&Vb, g_V);
    cudaGetSymbolAddress((void**)&Ab, g_A);
    cudaFuncSetAttribute(flash_attn, cudaFuncAttributeMaxDynamicSharedMemorySize,
                         ATT_SMEM);

    dim3 blk(256);
    dim3 gProj(DINNER / GBN, MROWS / GBM);   // (4, 64)

    gemm_tf32<<<gProj, blk>>>(x,   Wq, Qb, nullptr, MROWS, DINNER, SQD);
    gemm_tf32<<<gProj, blk>>>(ctx, Wk, Kb, nullptr, MROWS, DINNER, SCD);
    gemm_tf32<<<gProj, blk>>>(ctx, Wv, Vb, nullptr, MROWS, DINNER, SCD);
    flash_attn<<<dim3(SQL / 256, NHEADS, NB), blk, ATT_SMEM>>>(Qb, Kb, Vb, Ab);
    gemm_tf32<<<dim3(SQD / GBN, MROWS / GBM), blk>>>(Ab, Wo, out, bo,
                                                     MROWS, SQD, DINNER);
}

// round 8
// speedup vs baseline: 1.5315x; 1.1285x over previous
#include <cuda_runtime.h>
#include <cuda_fp16.h>
#include <cstdint>
#include <cstddef>

// Problem constants
#define NB      2
#define SQL     4096
#define SKL     4096
#define SQD     512
#define SCD     768
#define NHEADS  8
#define HDIM    64
#define DINNER  512
#define MROWS   (NB*SQL)   // 8192

#define QSCALE  (0.125f * 1.44269504088896340736f)   // dh^-1/2 * log2(e)

// Scratch (allocation-free rule: __device__ globals)
__device__ float  g_Q[(size_t)MROWS * DINNER];   // pre-scaled, tf32, pair-packed
__device__ float  g_K[(size_t)MROWS * DINNER];   // tf32, pair-packed
__device__ __half g_V[(size_t)MROWS * DINNER];   // fp16
__device__ float  g_A[(size_t)MROWS * DINNER];   // attention out, fp32

// ---------------------------------------------------------------------------
// helpers
// ---------------------------------------------------------------------------
__device__ __forceinline__ unsigned f2tf(float x) {
    unsigned u;
    asm("cvt.rna.tf32.f32 %0, %1;" : "=r"(u) : "f"(x));
    return u;
}
__device__ __forceinline__ float tf32r(float x) { return __uint_as_float(f2tf(x)); }

__device__ __forceinline__ float ex2(float x) {
    float r;
    asm("ex2.approx.ftz.f32 %0, %1;" : "=f"(r) : "f"(x));
    return r;
}

__device__ __forceinline__ unsigned packh2(float a, float b) {
    __half2 h = __floats2half2_rn(a, b);
    return *reinterpret_cast<unsigned*>(&h);
}

// D = A(16x8, tf32, row) * B(8x8, tf32, col) + C, fp32 accum
__device__ __forceinline__ void mma8(float* c,
                                     unsigned a0, unsigned a1, unsigned a2, unsigned a3,
                                     unsigned b0, unsigned b1) {
    asm volatile(
        "mma.sync.aligned.m16n8k8.row.col.f32.tf32.tf32.f32 "
        "{%0,%1,%2,%3}, {%4,%5,%6,%7}, {%8,%9}, {%0,%1,%2,%3};\n"
        : "+f"(c[0]), "+f"(c[1]), "+f"(c[2]), "+f"(c[3])
        : "r"(a0), "r"(a1), "r"(a2), "r"(a3), "r"(b0), "r"(b1));
}

// D = A(16x16, f16, row) * B(16x8, f16, col) + C, fp32 accum
__device__ __forceinline__ void mma16h(float* c,
                                       unsigned a0, unsigned a1, unsigned a2, unsigned a3,
                                       unsigned b0, unsigned b1) {
    asm volatile(
        "mma.sync.aligned.m16n8k16.row.col.f32.f16.f16.f32 "
        "{%0,%1,%2,%3}, {%4,%5,%6,%7}, {%8,%9}, {%0,%1,%2,%3};\n"
        : "+f"(c[0]), "+f"(c[1]), "+f"(c[2]), "+f"(c[3])
        : "r"(a0), "r"(a1), "r"(a2), "r"(a3), "r"(b0), "r"(b1));
}

__device__ __forceinline__ void ldsm4t(unsigned* r, uint32_t addr) {
    asm volatile(
        "ldmatrix.sync.aligned.m8n8.x4.trans.shared.b16 {%0,%1,%2,%3}, [%4];"
        : "=r"(r[0]), "=r"(r[1]), "=r"(r[2]), "=r"(r[3]) : "r"(addr));
}

#define CP_ASYNC16(dst, src) \
    asm volatile("cp.async.cg.shared.global [%0], [%1], 16;" :: "r"(dst), "l"(src))
#define CP_COMMIT() asm volatile("cp.async.commit_group;")
#define CP_WAIT0()  asm volatile("cp.async.wait_group 0;")

// pair-pack permutation within an 8-col group: (t, t+4) pairs become adjacent
__device__ __forceinline__ int ppperm(int o) { return (o < 4) ? 2 * o : 2 * o - 7; }

// ---------------------------------------------------------------------------
// Generic TF32 GEMM: C[M,N] = A[M,K] @ B[K,N] (+bias), epilogue modes:
//   0: fp32 (+bias if bias != nullptr)
//   1: Q  — scale by QSCALE, tf32 round, pair-pack columns per 8-group
//   2: K  — tf32 round, pair-pack columns
//   3: V  — fp16 (half2 stores)
// ---------------------------------------------------------------------------
#define GBM 128
#define GBN 128
#define GBK 16
#define ASTR 20
#define BSTR 136

__global__ __launch_bounds__(256, 2) void gemm_tf32(
    const float* __restrict__ A, const float* __restrict__ B,
    void* __restrict__ Cv, const float* __restrict__ bias,
    int M, int N, int K, int mode)
{
    __shared__ __align__(16) float As[GBM * ASTR];
    __shared__ __align__(16) float Bs[GBK * BSTR];

    const int tid  = threadIdx.x;
    const int warp = tid >> 5, lane = tid & 31;
    const int g = lane >> 2, t = lane & 3;
    const int wm = warp >> 2, wn = warp & 3;
    const int mBase = blockIdx.y * GBM;
    const int nBase = blockIdx.x * GBN;

    float acc[4][4][4];
#pragma unroll
    for (int i = 0; i < 4; i++)
#pragma unroll
        for (int j = 0; j < 4; j++)
#pragma unroll
            for (int c = 0; c < 4; c++) acc[i][j][c] = 0.f;

#pragma unroll 1
    for (int k0 = 0; k0 < K; k0 += GBK) {
#pragma unroll
        for (int i = 0; i < 2; i++) {
            int idx = tid + i * 256;
            int r = idx >> 2, c4 = (idx & 3) * 4;
            float4 v = *(const float4*)(A + (size_t)(mBase + r) * K + k0 + c4);
            v.x = tf32r(v.x); v.y = tf32r(v.y); v.z = tf32r(v.z); v.w = tf32r(v.w);
            *(float4*)(As + r * ASTR + c4) = v;
        }
#pragma unroll
        for (int i = 0; i < 2; i++) {
            int idx = tid + i * 256;
            int r = idx >> 5, c4 = (idx & 31) * 4;
            float4 v = *(const float4*)(B + (size_t)(k0 + r) * N + nBase + c4);
            v.x = tf32r(v.x); v.y = tf32r(v.y); v.z = tf32r(v.z); v.w = tf32r(v.w);
            *(float4*)(Bs + r * BSTR + c4) = v;
        }
        __syncthreads();

#pragma unroll
        for (int kk = 0; kk < 2; kk++) {
            unsigned af[4][4];
#pragma unroll
            for (int mf = 0; mf < 4; mf++) {
                int rb = (wm * 64 + mf * 16 + g) * ASTR + kk * 8 + t;
                af[mf][0] = __float_as_uint(As[rb]);
                af[mf][1] = __float_as_uint(As[rb + 8 * ASTR]);
                af[mf][2] = __float_as_uint(As[rb + 4]);
                af[mf][3] = __float_as_uint(As[rb + 8 * ASTR + 4]);
            }
            unsigned bf[4][2];
#pragma unroll
            for (int nf = 0; nf < 4; nf++) {
                int cb = wn * 32 + nf * 8 + g;
                bf[nf][0] = __float_as_uint(Bs[(kk * 8 + t) * BSTR + cb]);
                bf[nf][1] = __float_as_uint(Bs[(kk * 8 + t + 4) * BSTR + cb]);
            }
#pragma unroll
            for (int mf = 0; mf < 4; mf++)
#pragma unroll
                for (int nf = 0; nf < 4; nf++)
                    mma8(acc[mf][nf], af[mf][0], af[mf][1], af[mf][2], af[mf][3],
                         bf[nf][0], bf[nf][1]);
        }
        __syncthreads();
    }

    // epilogue
#pragma unroll
    for (int mf = 0; mf < 4; mf++) {
        int r0 = mBase + wm * 64 + mf * 16 + g;
#pragma unroll
        for (int nf = 0; nf < 4; nf++) {
            int col = nBase + wn * 32 + nf * 8 + 2 * t;
            if (mode == 0) {
                float* C = (float*)Cv;
                float b0 = 0.f, b1 = 0.f;
                if (bias) { b0 = bias[col]; b1 = bias[col + 1]; }
                *(float2*)(C + (size_t)r0 * N + col) =
                    make_float2(acc[mf][nf][0] + b0, acc[mf][nf][1] + b1);
                *(float2*)(C + (size_t)(r0 + 8) * N + col) =
                    make_float2(acc[mf][nf][2] + b0, acc[mf][nf][3] + b1);
            } else if (mode == 3) {
                __half* C = (__half*)Cv;
                *(__half2*)(C + (size_t)r0 * N + col) =
                    __floats2half2_rn(acc[mf][nf][0], acc[mf][nf][1]);
                *(__half2*)(C + (size_t)(r0 + 8) * N + col) =
                    __floats2half2_rn(acc[mf][nf][2], acc[mf][nf][3]);
            } else {
                float* C = (float*)Cv;
                float sc = (mode == 1) ? QSCALE : 1.f;
                int cb = col & ~7;
                int p0 = ppperm(col & 7), p1 = ppperm((col & 7) + 1);
                C[(size_t)r0 * N + cb + p0]       = tf32r(acc[mf][nf][0] * sc);
                C[(size_t)r0 * N + cb + p1]       = tf32r(acc[mf][nf][1] * sc);
                C[(size_t)(r0 + 8) * N + cb + p0] = tf32r(acc[mf][nf][2] * sc);
                C[(size_t)(r0 + 8) * N + cb + p1] = tf32r(acc[mf][nf][3] * sc);
            }
        }
    }
}

// ---------------------------------------------------------------------------
// Flash attention v4: 2 CTAs/SM. One CTA = (b, h, 256 q-rows), 8 warps,
// M=32 rows/warp, 32-key tiles. Q resident in smem (pair-packed tf32,
// pre-scaled), K/V cp.async double-buffered (K pair-packed tf32, V fp16).
// S via tf32 mma (Q,K A/B frags from smem LDS.64), P->A-frag conversion fully
// in registers (C-layout == packed f16 A-layout), PV via fp16 mma with V
// B-frags from ldmatrix.trans.
// ---------------------------------------------------------------------------
#define TKEY   32
#define NT     (SKL / TKEY)           // 128 tiles
#define QSTRW  72                     // Q smem row stride, words
#define KSTRW  72                     // K smem row stride, words
#define VSTRH  72                     // V smem row stride, halves
#define QBYTES (256 * QSTRW * 4)      // 73728
#define KBYTES (TKEY * KSTRW * 4)     // 9216
#define VBYTES (TKEY * VSTRH * 2)     // 4608
#define BUFB   (KBYTES + VBYTES)      // 13824
#define ATT_SMEM (QBYTES + 2 * BUFB)  // 101376 bytes

__global__ __launch_bounds__(256, 2) void flash_attn(
    const float* __restrict__ Qg_, const float* __restrict__ Kg_,
    const __half* __restrict__ Vg_, float* __restrict__ O)
{
    extern __shared__ __align__(128) char smc[];
    float* smQf = (float*)smc;
    const uint32_t smem_u32 = (uint32_t)__cvta_generic_to_shared(smc);

    const int tid  = threadIdx.x;
    const int warp = tid >> 5, lane = tid & 31;
    const int g = lane >> 2, t = lane & 3;
    const int h = blockIdx.y, b = blockIdx.z;

    const float*  Qg = Qg_ + ((size_t)b * SQL + blockIdx.x * 256) * DINNER + h * HDIM;
    const float*  Kg = Kg_ + (size_t)b * SKL * DINNER + h * HDIM;
    const __half* Vg = Vg_ + (size_t)b * SKL * DINNER + h * HDIM;
    float*        Ob = O   + ((size_t)b * SQL + blockIdx.x * 256) * DINNER + h * HDIM;

    // ---- async copy Q (256 rows x 256B) ----
#pragma unroll
    for (int i = 0; i < 16; i++) {
        int idx = tid + i * 256;
        int row = idx >> 4, ch = idx & 15;
        CP_ASYNC16(smem_u32 + row * (QSTRW * 4) + ch * 16,
                   Qg + (size_t)row * DINNER + ch * 4);
    }
    // ---- stage K/V tile 0 into buffer 0 ----
    {
        int row = tid >> 4, ch = tid & 15;
        uint32_t kd = smem_u32 + QBYTES;
        CP_ASYNC16(kd + row * (KSTRW * 4) + ch * 16,
                   Kg + (size_t)row * DINNER + ch * 4);
        CP_ASYNC16(kd + (row + 16) * (KSTRW * 4) + ch * 16,
                   Kg + (size_t)(row + 16) * DINNER + ch * 4);
        int vrow = tid >> 3, vch = tid & 7;
        CP_ASYNC16(kd + KBYTES + vrow * (VSTRH * 2) + vch * 16,
                   Vg + (size_t)vrow * DINNER + vch * 8);
    }
    CP_COMMIT();

    // ldmatrix lane geometry for V B-frags
    const int lm_r  = (lane & 7) | (((lane >> 3) & 1) << 3);   // 0..15
    const int lm_c8 = (lane >> 4) << 3;                        // 0 or 8 halves
    const uint32_t vLane = (uint32_t)(lm_r * VSTRH + lm_c8) * 2;

    float oacc[8][8];
#pragma unroll
    for (int nf = 0; nf < 8; nf++)
#pragma unroll
        for (int c = 0; c < 8; c++) oacc[nf][c] = 0.f;

    float mrow[4], lrow[4];
#pragma unroll
    for (int r = 0; r < 4; r++) { mrow[r] = -1e30f; lrow[r] = 0.f; }

    const int qrow = warp * 32 + g;   // local q row (lane's group base)

#pragma unroll 1
    for (int it = 0; it < NT; it++) {
        CP_WAIT0();
        __syncthreads();

        // issue next tile's copies while computing this one
        if (it + 1 < NT) {
            const float*  Kn = Kg + (size_t)(it + 1) * TKEY * DINNER;
            const __half* Vn = Vg + (size_t)(it + 1) * TKEY * DINNER;
            uint32_t kd = smem_u32 + QBYTES + ((it + 1) & 1) * BUFB;
            int row = tid >> 4, ch = tid & 15;
            CP_ASYNC16(kd + row * (KSTRW * 4) + ch * 16,
                       Kn + (size_t)row * DINNER + ch * 4);
            CP_ASYNC16(kd + (row + 16) * (KSTRW * 4) + ch * 16,
                       Kn + (size_t)(row + 16) * DINNER + ch * 4);
            int vrow = tid >> 3, vch = tid & 7;
            CP_ASYNC16(kd + KBYTES + vrow * (VSTRH * 2) + vch * 16,
                       Vn + (size_t)vrow * DINNER + vch * 8);
            CP_COMMIT();
        }

        const float*   Ksm  = (const float*)(smc + QBYTES + (it & 1) * BUFB);
        const uint32_t vbuf = smem_u32 + QBYTES + (it & 1) * BUFB + KBYTES + vLane;

        // ---- S = Q @ K^T : M=32 (2 m16), N=32 keys, K=64 dh (tf32) ----
        float s[4][8];
#pragma unroll
        for (int nf = 0; nf < 4; nf++)
#pragma unroll
            for (int c = 0; c < 8; c++) s[nf][c] = 0.f;
#pragma unroll
        for (int kk = 0; kk < 8; kk++) {
            // Q A-frags from smem (pair-packed: one LDS.64 = (a0,a2))
            float2 q00 = *(const float2*)(smQf + (size_t)qrow * QSTRW + kk * 8 + 2 * t);
            float2 q01 = *(const float2*)(smQf + (size_t)(qrow + 8) * QSTRW + kk * 8 + 2 * t);
            float2 q10 = *(const float2*)(smQf + (size_t)(qrow + 16) * QSTRW + kk * 8 + 2 * t);
            float2 q11 = *(const float2*)(smQf + (size_t)(qrow + 24) * QSTRW + kk * 8 + 2 * t);
#pragma unroll
            for (int nf = 0; nf < 4; nf++) {
                float2 kv = *(const float2*)(Ksm + (size_t)(nf * 8 + g) * KSTRW + kk * 8 + 2 * t);
                unsigned b0 = __float_as_uint(kv.x), b1 = __float_as_uint(kv.y);
                mma8(&s[nf][0], __float_as_uint(q00.x), __float_as_uint(q01.x),
                                __float_as_uint(q00.y), __float_as_uint(q01.y), b0, b1);
                mma8(&s[nf][4], __float_as_uint(q10.x), __float_as_uint(q11.x),
                                __float_as_uint(q10.y), __float_as_uint(q11.y), b0, b1);
            }
        }

        // ---- online softmax over 4 row-groups (base-2) ----
        float tm[4];
#pragma unroll
        for (int r = 0; r < 4; r++) tm[r] = -1e30f;
#pragma unroll
        for (int nf = 0; nf < 4; nf++) {
            tm[0] = fmaxf(tm[0], fmaxf(s[nf][0], s[nf][1]));
            tm[1] = fmaxf(tm[1], fmaxf(s[nf][2], s[nf][3]));
            tm[2] = fmaxf(tm[2], fmaxf(s[nf][4], s[nf][5]));
            tm[3] = fmaxf(tm[3], fmaxf(s[nf][6], s[nf][7]));
        }
#pragma unroll
        for (int r = 0; r < 4; r++) {
            tm[r] = fmaxf(tm[r], __shfl_xor_sync(0xffffffffu, tm[r], 1));
            tm[r] = fmaxf(tm[r], __shfl_xor_sync(0xffffffffu, tm[r], 2));
        }
        float nm[4], al[4], rs[4];
#pragma unroll
        for (int r = 0; r < 4; r++) {
            nm[r] = fmaxf(mrow[r], tm[r]);
            al[r] = ex2(mrow[r] - nm[r]);
            rs[r] = 0.f;
        }
#pragma unroll
        for (int nf = 0; nf < 4; nf++) {
            s[nf][0] = ex2(s[nf][0] - nm[0]);
            s[nf][1] = ex2(s[nf][1] - nm[0]);
            s[nf][2] = ex2(s[nf][2] - nm[1]);
            s[nf][3] = ex2(s[nf][3] - nm[1]);
            s[nf][4] = ex2(s[nf][4] - nm[2]);
            s[nf][5] = ex2(s[nf][5] - nm[2]);
            s[nf][6] = ex2(s[nf][6] - nm[3]);
            s[nf][7] = ex2(s[nf][7] - nm[3]);
            rs[0] += s[nf][0] + s[nf][1]; rs[1] += s[nf][2] + s[nf][3];
            rs[2] += s[nf][4] + s[nf][5]; rs[3] += s[nf][6] + s[nf][7];
        }
#pragma unroll
        for (int r = 0; r < 4; r++) {
            rs[r] += __shfl_xor_sync(0xffffffffu, rs[r], 1);
            rs[r] += __shfl_xor_sync(0xffffffffu, rs[r], 2);
            lrow[r] = lrow[r] * al[r] + rs[r];
            mrow[r] = nm[r];
        }
#pragma unroll
        for (int nf = 0; nf < 8; nf++) {
            oacc[nf][0] *= al[0]; oacc[nf][1] *= al[0];
            oacc[nf][2] *= al[1]; oacc[nf][3] *= al[1];
            oacc[nf][4] *= al[2]; oacc[nf][5] *= al[2];
            oacc[nf][6] *= al[3]; oacc[nf][7] *= al[3];
        }

        // ---- O += P @ V : fp16 m16n8k16; A-frags built in registers ----
#pragma unroll
        for (int kk = 0; kk < 2; kk++) {
            // P A-frags: fp32 C-layout == packed f16 A-layout
            unsigned a0 = packh2(s[2*kk][0],     s[2*kk][1]);
            unsigned a1 = packh2(s[2*kk][2],     s[2*kk][3]);
            unsigned a2 = packh2(s[2*kk + 1][0], s[2*kk + 1][1]);
            unsigned a3 = packh2(s[2*kk + 1][2], s[2*kk + 1][3]);
            unsigned a4 = packh2(s[2*kk][4],     s[2*kk][5]);
            unsigned a5 = packh2(s[2*kk][6],     s[2*kk][7]);
            unsigned a6 = packh2(s[2*kk + 1][4], s[2*kk + 1][5]);
            unsigned a7 = packh2(s[2*kk + 1][6], s[2*kk + 1][7]);
            unsigned vb[4][4];
#pragma unroll
            for (int np = 0; np < 4; np++)
                ldsm4t(vb[np], vbuf + kk * (16 * VSTRH * 2) + np * 32);
#pragma unroll
            for (int nf = 0; nf < 8; nf++) {
                unsigned b0 = vb[nf >> 1][(nf & 1) * 2];
                unsigned b1 = vb[nf >> 1][(nf & 1) * 2 + 1];
                mma16h(&oacc[nf][0], a0, a1, a2, a3, b0, b1);
                mma16h(&oacc[nf][4], a4, a5, a6, a7, b0, b1);
            }
        }
    }

    // ---- epilogue: divide by row sums, write fp32 [B, QL, H*DH] ----
    float inv[4];
#pragma unroll
    for (int r = 0; r < 4; r++) inv[r] = 1.0f / lrow[r];
#pragma unroll
    for (int nf = 0; nf < 8; nf++) {
        int col = nf * 8 + 2 * t;
        *(float2*)(Ob + (size_t)qrow * DINNER + col) =
            make_float2(oacc[nf][0] * inv[0], oacc[nf][1] * inv[0]);
        *(float2*)(Ob + (size_t)(qrow + 8) * DINNER + col) =
            make_float2(oacc[nf][2] * inv[1], oacc[nf][3] * inv[1]);
        *(float2*)(Ob + (size_t)(qrow + 16) * DINNER + col) =
            make_float2(oacc[nf][4] * inv[2], oacc[nf][5] * inv[2]);
        *(float2*)(Ob + (size_t)(qrow + 24) * DINNER + col) =
            make_float2(oacc[nf][6] * inv[3], oacc[nf][7] * inv[3]);
    }
}

// ---------------------------------------------------------------------------
// launch
// ---------------------------------------------------------------------------
extern "C" void kernel_launch(void* const* d_in, const int* in_sizes, int n_in,
                              void* d_out, int out_size)
{
    (void)in_sizes; (void)n_in; (void)out_size;
    const float* x   = (const float*)d_in[0];
    const float* ctx = (const float*)d_in[1];
    const float* Wq  = (const float*)d_in[2];
    const float* Wk  = (const float*)d_in[3];
    const float* Wv  = (const float*)d_in[4];
    const float* Wo  = (const float*)d_in[5];
    const float* bo  = (const float*)d_in[6];
    float* out = (float*)d_out;

    float *Qb, *Kb, *Ab;
    __half* Vb;
    cudaGetSymbolAddress((void**)&Qb, g_Q);
    cudaGetSymbolAddress((void**)&Kb, g_K);
    cudaGetSymbolAddress((void**)&Vb, g_V);
    cudaGetSymbolAddress((void**)&Ab, g_A);
    cudaFuncSetAttribute(flash_attn, cudaFuncAttributeMaxDynamicSharedMemorySize,
                         ATT_SMEM);

    dim3 blk(256);
    dim3 gProj(DINNER / GBN, MROWS / GBM);   // (4, 64)

    gemm_tf32<<<gProj, blk>>>(x,   Wq, Qb, nullptr, MROWS, DINNER, SQD, 1);
    gemm_tf32<<<gProj, blk>>>(ctx, Wk, Kb, nullptr, MROWS, DINNER, SCD, 2);
    gemm_tf32<<<gProj, blk>>>(ctx, Wv, Vb, nullptr, MROWS, DINNER, SCD, 3);
    flash_attn<<<dim3(SQL / 256, NHEADS, NB), blk, ATT_SMEM>>>(Qb, Kb, Vb, Ab);
    gemm_tf32<<<dim3(SQD / GBN, MROWS / GBM), blk>>>(Ab, Wo, out, bo,
                                                     MROWS, SQD, DINNER, 0);
}